// round 4
// baseline (speedup 1.0000x reference)
#include <cuda_runtime.h>
#include <math.h>

#define BB   128
#define SS   512
#define CC   256
#define DOO  4
#define GG   10
#define NCTA 128
#define TPB  1024

#define OUT_PI   (BB*SS*DOO)                    /* 262144  */
#define OUT_SG   (OUT_PI + BB*SS*GG)            /* 917504  */
#define OUT_MU   (OUT_SG + BB*SS*GG*DOO)        /* 3538944 */
#define OUT_MASK (OUT_MU + BB*SS*GG*DOO)        /* 6160384 */

// ---------------- scratch (static device globals; no cudaMalloc) ------------
__device__ float g_pn[BB*SS*DOO];                 // prenet output [b][s][d]
__device__ float g_gi0[(size_t)SS*768*BB];        // x@Wih0^T + bih0, layout [s][col][b]
__device__ float g_h0[2][256*BB];                 // h0 double buffer, [u][b]
__device__ float g_h1[2][256*BB];                 // h1 double buffer, [u][b]
__device__ float g_H[(size_t)SS*256*BB];          // h1 history, [s][u][b]
__device__ unsigned int g_arr[NCTA*32];           // arrive flags, 128B stride

__device__ __forceinline__ float sigmoidf_(float x){ return 1.f/(1.f + expf(-x)); }

__device__ __forceinline__ void ffma2(unsigned long long &acc,
                                      unsigned long long a, unsigned long long b){
    asm("fma.rn.f32x2 %0, %1, %2, %0;" : "+l"(acc) : "l"(a), "l"(b));
}
__device__ __forceinline__ float2 u2f2(unsigned long long v){
    float2 f; asm("mov.b64 {%0,%1}, %2;" : "=f"(f.x), "=f"(f.y) : "l"(v)); return f;
}

// all-peers grid barrier, release/acquire (no full membar). Flags reset by init.
__device__ __forceinline__ void gbar(unsigned int tgt){
    __syncthreads();
    if (threadIdx.x == 0){
        asm volatile("st.release.gpu.global.u32 [%0], %1;"
                     :: "l"(&g_arr[blockIdx.x*32]), "r"(tgt) : "memory");
    }
    if (threadIdx.x < NCTA){
        unsigned int v;
        do {
            asm volatile("ld.acquire.gpu.global.u32 %0, [%1];"
                         : "=r"(v) : "l"(&g_arr[threadIdx.x*32]) : "memory");
        } while (v < tgt);
    }
    __syncthreads();
}

// ---------------- kernel 0: per-launch state reset ---------------------------
__global__ void init_kernel(){
    int i = blockIdx.x*256 + threadIdx.x;   // grid 128*256 = 32768
    if (i < NCTA*32) g_arr[i] = 0u;
    g_h0[0][i] = 0.f; g_h0[1][i] = 0.f;
    g_h1[0][i] = 0.f; g_h1[1][i] = 0.f;
}

// ---------------- kernel 1: prenet = prev @ W_pre^T + b_pre -----------------
__global__ void prenet_kernel(const float* __restrict__ tgt,
                              const float* __restrict__ W_pre,
                              const float* __restrict__ b_pre){
    int idx = blockIdx.x*256 + threadIdx.x;
    if (idx >= BB*SS*DOO) return;
    int d = idx & 3;
    int s = (idx >> 2) & (SS-1);
    int b = idx >> 11;
    float v = b_pre[d];
    if (s > 0){
        const float* pv = tgt + ((size_t)(b*SS + s - 1))*DOO;
        #pragma unroll
        for (int e = 0; e < 4; e++) v += pv[e]*W_pre[d*DOO + e];
    }
    g_pn[idx] = v;
}

// ---------------- kernel 2: gi0 = xs @ Wih0^T + bih0 (FFMA2) ----------------
__global__ __launch_bounds__(256) void gi0_gemm(const float* __restrict__ enc,
                                                const float* __restrict__ Wih0,
                                                const float* __restrict__ bih0){
    __shared__ float As[32][68];
    __shared__ float Wd[32][132];   // duplicated col pairs
    const int s  = blockIdx.z;
    const int c0 = blockIdx.y * 64;
    const int b0 = blockIdx.x * 64;
    const int t  = threadIdx.x;
    const int bg = t & 15, cg = t >> 4;
    unsigned long long acc[4][2];
    #pragma unroll
    for (int i = 0; i < 4; i++){ acc[i][0] = 0ULL; acc[i][1] = 0ULL; }

    for (int kk = 0; kk < 260; kk += 32){
        for (int i = t; i < 2048; i += 256){
            int k = i >> 6, b = i & 63;
            int kg = kk + k;
            float v = 0.f;
            if (kg < 260){
                if (kg < 256) v = enc[(((size_t)(b0+b))*SS + s)*CC + kg];
                else          v = g_pn[(((size_t)(b0+b))*SS + s)*DOO + (kg-256)];
            }
            As[k][b] = v;
        }
        for (int i = t; i < 2048; i += 256){
            int k = i >> 6, c = i & 63;
            int kg = kk + k;
            float v = (kg < 260) ? Wih0[(size_t)(c0+c)*260 + kg] : 0.f;
            Wd[k][2*c]   = v;
            Wd[k][2*c+1] = v;
        }
        __syncthreads();
        #pragma unroll 8
        for (int k = 0; k < 32; k++){
            ulonglong2 a   = *(const ulonglong2*)&As[k][bg*4];
            ulonglong2 w01 = *(const ulonglong2*)&Wd[k][cg*8];
            ulonglong2 w23 = *(const ulonglong2*)&Wd[k][cg*8+4];
            ffma2(acc[0][0], a.x, w01.x); ffma2(acc[0][1], a.y, w01.x);
            ffma2(acc[1][0], a.x, w01.y); ffma2(acc[1][1], a.y, w01.y);
            ffma2(acc[2][0], a.x, w23.x); ffma2(acc[2][1], a.y, w23.x);
            ffma2(acc[3][0], a.x, w23.y); ffma2(acc[3][1], a.y, w23.y);
        }
        __syncthreads();
    }
    #pragma unroll
    for (int ci = 0; ci < 4; ci++){
        int c = c0 + cg*4 + ci;
        float bias = bih0[c];
        float2 p0 = u2f2(acc[ci][0]);
        float2 p1 = u2f2(acc[ci][1]);
        float4 o = make_float4(p0.x+bias, p0.y+bias, p1.x+bias, p1.y+bias);
        *(float4*)&g_gi0[((size_t)s*768 + c)*BB + b0 + bg*4] = o;
    }
}

// ---------------- kernel 3: persistent GRU recurrence, 1 barrier/phase ------
// Phase ph (0..512): h0_out[ph] = GRU0(x[ph], h0_out[ph-1])          (ph<512)
//                    h1_out[ph-1] = GRU1(h0_out[ph-1], h1_out[ph-2]) (ph>=1)
// 128 CTAs = 64 unit-groups (4 units) x 2 batch-halves (64 batches), 1024 thr.
// 36 gate-rows: rows 0-11 gh0(Whh0), 12-23 gi1(Wih1), 24-35 gh1(Whh1).
__global__ void __launch_bounds__(TPB, 1) rec_kernel(
    const float* __restrict__ Whh0, const float* __restrict__ bhh0,
    const float* __restrict__ Wih1, const float* __restrict__ bih1,
    const float* __restrict__ Whh1, const float* __restrict__ bhh1)
{
    extern __shared__ float sm[];
    float* wAd = sm;                 // 36*512  : dup weight rows      (72 KB)
    float* hs0 = wAd + 36*512;       // 256*64  : h0_out[ph-1] staging (64 KB)
    float* hs1 = hs0 + 16384;        // 256*64  : h1_out[ph-2] staging (64 KB)
    float* pA  = hs1 + 16384;        // 2*24*64 : partials rows 0-23 (2 k-halves)
    float* pC  = pA + 3072;          // 2*12*64 : partials rows 24-35

    const int t = threadIdx.x;
    const int w = t >> 5, l = t & 31;
    const int ug = blockIdx.x >> 1, bh = blockIdx.x & 1;
    const int u0 = ug*4, b0 = bh*64;

    // ---- load 36 weight rows (duplicated pairs for FFMA2), resident all run
    for (int i = t; i < 36*256; i += TPB){
        int row = i >> 8, k = i & 255;
        int g3 = row/12, rr = row - g3*12;
        int ui2 = rr/3, g = rr - ui2*3;
        const float* W = (g3 == 0) ? Whh0 : (g3 == 1) ? Wih1 : Whh1;
        float v = W[(size_t)(g*256 + u0 + ui2)*256 + k];
        wAd[row*512 + 2*k]   = v;
        wAd[row*512 + 2*k+1] = v;
    }

    // ---- per-thread update constants (threads 0..255: 4 units x 64 batches)
    const int ui = (t & 255) >> 6;
    const int bl = t & 63;
    const int u  = u0 + ui;
    float b0r=0,b0z=0,b0n=0,b1ir=0,b1iz=0,b1in=0,b1hr=0,b1hz=0,b1hn=0;
    if (t < 256){
        b0r=bhh0[u]; b0z=bhh0[256+u]; b0n=bhh0[512+u];
        b1ir=bih1[u]; b1iz=bih1[256+u]; b1in=bih1[512+u];
        b1hr=bhh1[u]; b1hz=bhh1[256+u]; b1hn=bhh1[512+u];
    }

    for (int ph = 0; ph < 513; ph++){
        // ------- stage h0_out[ph-1] and h1_out[ph-2] (one shot) -------------
        const float* src0 = g_h0[(ph+1) & 1];
        const float* src1 = g_h1[ph & 1];
        for (int i = t; i < 8192; i += TPB){
            int j = i & 4095; int k = j >> 4, b4 = j & 15;
            if (i < 4096) ((float4*)hs0)[j] = __ldcg((const float4*)&src0[k*BB + b0 + b4*4]);
            else          ((float4*)hs1)[j] = __ldcg((const float4*)&src1[k*BB + b0 + b4*4]);
        }
        // prefetch gi0 for GRU0 update
        float gir=0.f, giz=0.f, gin=0.f;
        if (t < 256 && ph < 512){
            const float* gb = g_gi0 + (size_t)ph*768*BB;
            gir = __ldcg(&gb[(size_t)u*BB       + b0 + bl]);
            giz = __ldcg(&gb[(size_t)(256+u)*BB + b0 + bl]);
            gin = __ldcg(&gb[(size_t)(512+u)*BB + b0 + bl]);
        }
        __syncthreads();

        // ------- fused 3-GEMM: 36 rows x 64 batch x 256 k -------------------
        if (w < 24){
            // rows 0..23 (hs0): 12 row-pairs x 2 k-halves
            const int kh = w & 1, rg = w >> 1;          // rg 0..11 -> rows 2rg, 2rg+1
            const float* hp = hs0 + kh*(128*64) + (l << 1);
            const float* wd = wAd + (2*rg)*512 + kh*256;
            unsigned long long a0=0ULL, a1=0ULL;
            #pragma unroll 8
            for (int k = 0; k < 128; k += 4){
                ulonglong2 w00 = *(const ulonglong2*)(wd + 2*k);
                ulonglong2 w01 = *(const ulonglong2*)(wd + 2*k + 4);
                ulonglong2 w10 = *(const ulonglong2*)(wd + 512 + 2*k);
                ulonglong2 w11 = *(const ulonglong2*)(wd + 512 + 2*k + 4);
                unsigned long long hA = *(const unsigned long long*)(hp + k*64);
                unsigned long long hB = *(const unsigned long long*)(hp + (k+1)*64);
                unsigned long long hC = *(const unsigned long long*)(hp + (k+2)*64);
                unsigned long long hD = *(const unsigned long long*)(hp + (k+3)*64);
                ffma2(a0, hA, w00.x); ffma2(a1, hA, w10.x);
                ffma2(a0, hB, w00.y); ffma2(a1, hB, w10.y);
                ffma2(a0, hC, w01.x); ffma2(a1, hC, w11.x);
                ffma2(a0, hD, w01.y); ffma2(a1, hD, w11.y);
            }
            float* pa = pA + (kh*24 + 2*rg)*64 + (l << 1);
            *(float2*)&pa[0]  = u2f2(a0);
            *(float2*)&pa[64] = u2f2(a1);
        } else {
            // rows 24..35 (hs1): 4 row-triples x 2 k-halves
            const int q = w - 24;
            const int kh = q & 1, rg = q >> 1;          // rg 0..3 -> pC rows 3rg..3rg+2
            const float* hp = hs1 + kh*(128*64) + (l << 1);
            const float* wd = wAd + (24 + 3*rg)*512 + kh*256;
            unsigned long long c0=0ULL, c1=0ULL, c2=0ULL;
            #pragma unroll 8
            for (int k = 0; k < 128; k += 2){
                ulonglong2 w0 = *(const ulonglong2*)(wd + 2*k);
                ulonglong2 w1 = *(const ulonglong2*)(wd + 512  + 2*k);
                ulonglong2 w2 = *(const ulonglong2*)(wd + 1024 + 2*k);
                unsigned long long hA = *(const unsigned long long*)(hp + k*64);
                unsigned long long hB = *(const unsigned long long*)(hp + (k+1)*64);
                ffma2(c0, hA, w0.x); ffma2(c1, hA, w1.x); ffma2(c2, hA, w2.x);
                ffma2(c0, hB, w0.y); ffma2(c1, hB, w1.y); ffma2(c2, hB, w2.y);
            }
            float* pc = pC + (kh*12 + 3*rg)*64 + (l << 1);
            *(float2*)&pc[0]   = u2f2(c0);
            *(float2*)&pc[64]  = u2f2(c1);
            *(float2*)&pc[128] = u2f2(c2);
        }
        __syncthreads();

        // ------- elementwise updates (threads 0..255) ------------------------
        if (t < 256){
            int r0 = ui*3;
            if (ph < 512){
                float s0 = pA[r0*64+bl]     + pA[(24+r0)*64+bl];
                float s1 = pA[(r0+1)*64+bl] + pA[(24+r0+1)*64+bl];
                float s2 = pA[(r0+2)*64+bl] + pA[(24+r0+2)*64+bl];
                float r = sigmoidf_(gir + s0 + b0r);
                float z = sigmoidf_(giz + s1 + b0z);
                float n = tanhf(gin + r*(s2 + b0n));
                float hold = hs0[u*64 + bl];
                float hnew = (1.f - z)*n + z*hold;
                g_h0[ph & 1][u*BB + b0 + bl] = 0.1f*hold + 0.9f*hnew;
            }
            if (ph >= 1){
                int q0 = 12 + r0;
                float i0 = pA[q0*64+bl]     + pA[(24+q0)*64+bl]   + b1ir;
                float i1 = pA[(q0+1)*64+bl] + pA[(24+q0+1)*64+bl] + b1iz;
                float i2 = pA[(q0+2)*64+bl] + pA[(24+q0+2)*64+bl] + b1in;
                float hg0 = pC[r0*64+bl]     + pC[(12+r0)*64+bl]     + b1hr;
                float hg1 = pC[(r0+1)*64+bl] + pC[(12+r0+1)*64+bl]   + b1hz;
                float hg2 = pC[(r0+2)*64+bl] + pC[(12+r0+2)*64+bl]   + b1hn;
                float r = sigmoidf_(i0 + hg0);
                float z = sigmoidf_(i1 + hg1);
                float n = tanhf(i2 + r*hg2);
                float hold = hs1[u*64 + bl];
                float hnew = (1.f - z)*n + z*hold;
                float hout = 0.1f*hold + 0.9f*hnew;
                g_h1[(ph+1) & 1][u*BB + b0 + bl] = hout;
                g_H[((size_t)(ph-1)*256 + u)*BB + b0 + bl] = hout;
            }
        }
        gbar((unsigned int)(ph+1));
    }
}

// ---------------- kernel 4: MDN head GEMM + epilogue (FFMA2) ----------------
__global__ __launch_bounds__(256) void out_gemm(const float* __restrict__ enc,
    const float* __restrict__ Wpi, const float* __restrict__ bpi,
    const float* __restrict__ Wsg, const float* __restrict__ bsg,
    const float* __restrict__ Wmu, const float* __restrict__ bmu,
    float* __restrict__ out)
{
    __shared__ float As[32][68];
    __shared__ float Wd[32][196];   // 96 cols duplicated
    __shared__ float Rs[64][96];
    const int s  = blockIdx.y;
    const int b0 = blockIdx.x * 64;
    const int t  = threadIdx.x;
    const int bg = t & 15, cg = t >> 4;
    unsigned long long acc[6][2];
    #pragma unroll
    for (int i = 0; i < 6; i++){ acc[i][0] = 0ULL; acc[i][1] = 0ULL; }

    for (int kk = 0; kk < 512; kk += 32){
        for (int i = t; i < 2048; i += 256){
            int k = i >> 6, b = i & 63;
            int kg = kk + k;
            float v;
            if (kg < 256) v = g_H[((size_t)s*256 + kg)*BB + b0 + b];
            else          v = enc[(((size_t)(b0+b))*SS + s)*CC + (kg-256)];
            As[k][b] = v;
        }
        for (int i = t; i < 32*96; i += 256){
            int k = i/96, c = i - k*96;
            int kg = kk + k;
            float v = 0.f;
            if      (c < 10) v = Wpi[(size_t)c*512 + kg];
            else if (c < 50) v = Wsg[(size_t)(c-10)*512 + kg];
            else if (c < 90) v = Wmu[(size_t)(c-50)*512 + kg];
            Wd[k][2*c]   = v;
            Wd[k][2*c+1] = v;
        }
        __syncthreads();
        #pragma unroll 4
        for (int k = 0; k < 32; k++){
            ulonglong2 a   = *(const ulonglong2*)&As[k][bg*4];
            ulonglong2 w01 = *(const ulonglong2*)&Wd[k][cg*12];
            ulonglong2 w23 = *(const ulonglong2*)&Wd[k][cg*12+4];
            ulonglong2 w45 = *(const ulonglong2*)&Wd[k][cg*12+8];
            ffma2(acc[0][0], a.x, w01.x); ffma2(acc[0][1], a.y, w01.x);
            ffma2(acc[1][0], a.x, w01.y); ffma2(acc[1][1], a.y, w01.y);
            ffma2(acc[2][0], a.x, w23.x); ffma2(acc[2][1], a.y, w23.x);
            ffma2(acc[3][0], a.x, w23.y); ffma2(acc[3][1], a.y, w23.y);
            ffma2(acc[4][0], a.x, w45.x); ffma2(acc[4][1], a.y, w45.x);
            ffma2(acc[5][0], a.x, w45.y); ffma2(acc[5][1], a.y, w45.y);
        }
        __syncthreads();
    }
    #pragma unroll
    for (int ci = 0; ci < 6; ci++){
        int c = cg*6 + ci;
        float bias = (c < 10) ? bpi[c] : (c < 50) ? bsg[c-10] : (c < 90) ? bmu[c-50] : 0.f;
        float2 p0 = u2f2(acc[ci][0]);
        float2 p1 = u2f2(acc[ci][1]);
        Rs[bg*4+0][c] = p0.x + bias;
        Rs[bg*4+1][c] = p0.y + bias;
        Rs[bg*4+2][c] = p1.x + bias;
        Rs[bg*4+3][c] = p1.y + bias;
    }
    __syncthreads();

    if (t < 64){
        int b = b0 + t;
        float lv[10]; float m = -1e30f;
        #pragma unroll
        for (int g = 0; g < 10; g++){ lv[g] = Rs[t][g]; m = fmaxf(m, lv[g]); }
        float sum = 0.f;
        #pragma unroll
        for (int g = 0; g < 10; g++){ lv[g] = expf(lv[g]-m); sum += lv[g]; }
        float inv = 1.f/sum;
        size_t base = (size_t)OUT_PI + ((size_t)b*SS + s)*10;
        #pragma unroll
        for (int g = 0; g < 10; g++) out[base + g] = lv[g]*inv;
    }
    for (int i = t; i < 64*40; i += 256){
        int row = i/40, j = i - row*40;
        int b = b0 + row;
        float x  = Rs[row][10+j];
        float xm = Rs[row][50+j];
        size_t base = ((size_t)b*SS + s)*40 + j;
        out[(size_t)OUT_SG + base] = (x > 0.f) ? (x + 1.f) : expf(x);
        out[(size_t)OUT_MU + base] = xm;
    }
}

// ---------------- kernel 5: tgt copy + duration mask ------------------------
__global__ void tail_kernel(const float* __restrict__ tgt,
                            const int* __restrict__ dur,
                            float* __restrict__ out){
    if (blockIdx.x < 1024){
        int idx = blockIdx.x*256 + threadIdx.x;
        out[idx] = tgt[idx];
    } else {
        int b = blockIdx.x - 1024;
        __shared__ int cnt;
        if (threadIdx.x == 0) cnt = 0;
        __syncthreads();
        int local = 0;
        for (int s = threadIdx.x; s < SS; s += 256) local += (dur[b*SS + s] > 0) ? 1 : 0;
        #pragma unroll
        for (int o = 16; o; o >>= 1) local += __shfl_down_sync(0xffffffffu, local, o);
        if ((threadIdx.x & 31) == 0) atomicAdd(&cnt, local);
        __syncthreads();
        int c = cnt;
        for (int s = threadIdx.x; s < SS; s += 256)
            out[OUT_MASK + b*SS + s] = (s >= c) ? 1.f : 0.f;
    }
}

// ---------------- launch -----------------------------------------------------
#define REC_SMEM ((36*512 + 16384*2 + 3072 + 1536) * (int)sizeof(float))

extern "C" void kernel_launch(void* const* d_in, const int* in_sizes, int n_in,
                              void* d_out, int out_size)
{
    const float* enc   = (const float*)d_in[0];
    const float* tgt   = (const float*)d_in[1];
    const int*   dur   = (const int*)  d_in[2];
    const float* W_pre = (const float*)d_in[3];
    const float* b_pre = (const float*)d_in[4];
    const float* Wih0  = (const float*)d_in[5];
    const float* Whh0  = (const float*)d_in[6];
    const float* bih0  = (const float*)d_in[7];
    const float* bhh0  = (const float*)d_in[8];
    const float* Wih1  = (const float*)d_in[9];
    const float* Whh1  = (const float*)d_in[10];
    const float* bih1  = (const float*)d_in[11];
    const float* bhh1  = (const float*)d_in[12];
    const float* Wpi   = (const float*)d_in[13];
    const float* bpi   = (const float*)d_in[14];
    const float* Wsg   = (const float*)d_in[15];
    const float* bsg   = (const float*)d_in[16];
    const float* Wmu   = (const float*)d_in[17];
    const float* bmu   = (const float*)d_in[18];
    float* out = (float*)d_out;

    init_kernel<<<128, 256>>>();

    prenet_kernel<<<(BB*SS*DOO + 255)/256, 256>>>(tgt, W_pre, b_pre);

    dim3 g2(2, 12, SS);
    gi0_gemm<<<g2, 256>>>(enc, Wih0, bih0);

    cudaFuncSetAttribute(rec_kernel, cudaFuncAttributeMaxDynamicSharedMemorySize, REC_SMEM);
    rec_kernel<<<NCTA, TPB, REC_SMEM>>>(Whh0, bhh0, Wih1, bih1, Whh1, bhh1);

    dim3 g4(2, SS);
    out_gemm<<<g4, 256>>>(enc, Wpi, bpi, Wsg, bsg, Wmu, bmu, out);

    tail_kernel<<<1024 + BB, 256>>>(tgt, dur, out);
}

// round 5
// speedup vs baseline: 1.2229x; 1.2229x over previous
#include <cuda_runtime.h>
#include <math.h>

#define BB   128
#define SS   512
#define CC   256
#define DOO  4
#define GG   10
#define NCTA 128
#define TPB  512

#define OUT_PI   (BB*SS*DOO)                    /* 262144  */
#define OUT_SG   (OUT_PI + BB*SS*GG)            /* 917504  */
#define OUT_MU   (OUT_SG + BB*SS*GG*DOO)        /* 3538944 */
#define OUT_MASK (OUT_MU + BB*SS*GG*DOO)        /* 6160384 */

// ---------------- scratch (static device globals; no cudaMalloc) ------------
__device__ float g_pn[BB*SS*DOO];                 // prenet output [b][s][d]
__device__ float g_gi0[(size_t)SS*768*BB];        // x@Wih0^T + bih0, layout [s][col][b]
__device__ float g_h0[2][256*BB];                 // h0 double buffer, [u][b]
__device__ float g_h1[2][256*BB];                 // h1 double buffer, [u][b]
__device__ float g_H[(size_t)SS*256*BB];          // h1 history, [s][u][b]
__device__ __align__(16) unsigned int g_arr[NCTA]; // contiguous arrive flags (4 lines)

__device__ __forceinline__ float sigmoidf_(float x){ return 1.f/(1.f + expf(-x)); }

__device__ __forceinline__ void ffma2(unsigned long long &acc,
                                      unsigned long long a, unsigned long long b){
    asm("fma.rn.f32x2 %0, %1, %2, %0;" : "+l"(acc) : "l"(a), "l"(b));
}
__device__ __forceinline__ float2 u2f2(unsigned long long v){
    float2 f; asm("mov.b64 {%0,%1}, %2;" : "=f"(f.x), "=f"(f.y) : "l"(v)); return f;
}

// all-peers grid barrier, compact flags: warp 0 polls 128 flags as 32 x v4 loads
__device__ __forceinline__ void gbar(unsigned int tgt){
    __syncthreads();
    if (threadIdx.x == 0){
        __threadfence();
        *(volatile unsigned int*)&g_arr[blockIdx.x] = tgt;
    }
    if (threadIdx.x < 32){
        const unsigned int* p = &g_arr[threadIdx.x*4];
        bool done;
        do {
            unsigned int a,b,c,d;
            asm volatile("ld.volatile.global.v4.u32 {%0,%1,%2,%3}, [%4];"
                         : "=r"(a), "=r"(b), "=r"(c), "=r"(d) : "l"(p));
            unsigned int m = min(min(a,b), min(c,d));
            done = __all_sync(0xffffffffu, m >= tgt);
        } while (!done);
        __threadfence();
    }
    __syncthreads();
}

// ---------------- kernel 0: per-launch state reset ---------------------------
__global__ void init_kernel(){
    int i = blockIdx.x*256 + threadIdx.x;   // grid 128*256 = 32768
    if (i < NCTA) g_arr[i] = 0u;
    g_h0[0][i] = 0.f; g_h0[1][i] = 0.f;
    g_h1[0][i] = 0.f; g_h1[1][i] = 0.f;
}

// ---------------- kernel 1: prenet = prev @ W_pre^T + b_pre -----------------
__global__ void prenet_kernel(const float* __restrict__ tgt,
                              const float* __restrict__ W_pre,
                              const float* __restrict__ b_pre){
    int idx = blockIdx.x*256 + threadIdx.x;
    if (idx >= BB*SS*DOO) return;
    int d = idx & 3;
    int s = (idx >> 2) & (SS-1);
    int b = idx >> 11;
    float v = b_pre[d];
    if (s > 0){
        const float* pv = tgt + ((size_t)(b*SS + s - 1))*DOO;
        #pragma unroll
        for (int e = 0; e < 4; e++) v += pv[e]*W_pre[d*DOO + e];
    }
    g_pn[idx] = v;
}

// ---------------- kernel 2: gi0 = xs @ Wih0^T + bih0 (FFMA2) ----------------
__global__ __launch_bounds__(256) void gi0_gemm(const float* __restrict__ enc,
                                                const float* __restrict__ Wih0,
                                                const float* __restrict__ bih0){
    __shared__ float As[32][68];
    __shared__ float Wd[32][132];   // duplicated col pairs
    const int s  = blockIdx.z;
    const int c0 = blockIdx.y * 64;
    const int b0 = blockIdx.x * 64;
    const int t  = threadIdx.x;
    const int bg = t & 15, cg = t >> 4;
    unsigned long long acc[4][2];
    #pragma unroll
    for (int i = 0; i < 4; i++){ acc[i][0] = 0ULL; acc[i][1] = 0ULL; }

    for (int kk = 0; kk < 260; kk += 32){
        for (int i = t; i < 2048; i += 256){
            int k = i >> 6, b = i & 63;
            int kg = kk + k;
            float v = 0.f;
            if (kg < 260){
                if (kg < 256) v = enc[(((size_t)(b0+b))*SS + s)*CC + kg];
                else          v = g_pn[(((size_t)(b0+b))*SS + s)*DOO + (kg-256)];
            }
            As[k][b] = v;
        }
        for (int i = t; i < 2048; i += 256){
            int k = i >> 6, c = i & 63;
            int kg = kk + k;
            float v = (kg < 260) ? Wih0[(size_t)(c0+c)*260 + kg] : 0.f;
            Wd[k][2*c]   = v;
            Wd[k][2*c+1] = v;
        }
        __syncthreads();
        #pragma unroll 8
        for (int k = 0; k < 32; k++){
            ulonglong2 a   = *(const ulonglong2*)&As[k][bg*4];
            ulonglong2 w01 = *(const ulonglong2*)&Wd[k][cg*8];
            ulonglong2 w23 = *(const ulonglong2*)&Wd[k][cg*8+4];
            ffma2(acc[0][0], a.x, w01.x); ffma2(acc[0][1], a.y, w01.x);
            ffma2(acc[1][0], a.x, w01.y); ffma2(acc[1][1], a.y, w01.y);
            ffma2(acc[2][0], a.x, w23.x); ffma2(acc[2][1], a.y, w23.x);
            ffma2(acc[3][0], a.x, w23.y); ffma2(acc[3][1], a.y, w23.y);
        }
        __syncthreads();
    }
    #pragma unroll
    for (int ci = 0; ci < 4; ci++){
        int c = c0 + cg*4 + ci;
        float bias = bih0[c];
        float2 p0 = u2f2(acc[ci][0]);
        float2 p1 = u2f2(acc[ci][1]);
        float4 o = make_float4(p0.x+bias, p0.y+bias, p1.x+bias, p1.y+bias);
        *(float4*)&g_gi0[((size_t)s*768 + c)*BB + b0 + bg*4] = o;
    }
}

// ---------------- kernel 3: persistent GRU recurrence, 1 barrier/phase ------
// Phase ph (0..512): h0_out[ph] = GRU0(x[ph], h0_out[ph-1])          (ph<512)
//                    h1_out[ph-1] = GRU1(h0_out[ph-1], h1_out[ph-2]) (ph>=1)
// 128 CTAs = 64 unit-groups (4 units) x 2 batch-halves (64 batches), 512 thr.
// 36 gate-rows per CTA: rows 0-11 gh0(Whh0), 12-23 gi1(Wih1), 24-35 gh1(Whh1).
__global__ void __launch_bounds__(TPB, 1) rec_kernel(
    const float* __restrict__ Whh0, const float* __restrict__ bhh0,
    const float* __restrict__ Wih1, const float* __restrict__ bih1,
    const float* __restrict__ Whh1, const float* __restrict__ bhh1)
{
    extern __shared__ float sm[];
    float* wAd = sm;                 // 36*512  : dup weight rows      (72 KB)
    float* hs0 = wAd + 36*512;       // 256*64  : h0_out[ph-1] staging (64 KB)
    float* hs1 = hs0 + 16384;        // 256*64  : h1_out[ph-2] staging (64 KB)
    float* pA  = hs1 + 16384;        // 2*24*64 : partials rows 0-23 (2 k-halves)
    float* pC  = pA + 3072;          // 12*64   : full sums rows 24-35

    const int t = threadIdx.x;
    const int w = t >> 5, l = t & 31;
    const int ug = blockIdx.x >> 1, bh = blockIdx.x & 1;
    const int u0 = ug*4, b0 = bh*64;

    // ---- load 36 weight rows (duplicated pairs for FFMA2), resident all run
    for (int i = t; i < 36*256; i += TPB){
        int row = i >> 8, k = i & 255;
        int g3 = row/12, rr = row - g3*12;
        int ui2 = rr/3, g = rr - ui2*3;
        const float* W = (g3 == 0) ? Whh0 : (g3 == 1) ? Wih1 : Whh1;
        float v = W[(size_t)(g*256 + u0 + ui2)*256 + k];
        wAd[row*512 + 2*k]   = v;
        wAd[row*512 + 2*k+1] = v;
    }

    // ---- per-thread update constants (threads 0..255: 4 units x 64 batches)
    const int ui = (t & 255) >> 6;
    const int bl = t & 63;
    const int u  = u0 + ui;
    float b0r=0,b0z=0,b0n=0,b1ir=0,b1iz=0,b1in=0,b1hr=0,b1hz=0,b1hn=0;
    if (t < 256){
        b0r=bhh0[u]; b0z=bhh0[256+u]; b0n=bhh0[512+u];
        b1ir=bih1[u]; b1iz=bih1[256+u]; b1in=bih1[512+u];
        b1hr=bhh1[u]; b1hz=bhh1[256+u]; b1hn=bhh1[512+u];
    }

    for (int ph = 0; ph < 513; ph++){
        // ------- stage h0_out[ph-1] and h1_out[ph-2] (one shot) -------------
        const float* src0 = g_h0[(ph+1) & 1];
        const float* src1 = g_h1[ph & 1];
        for (int i = t; i < 8192; i += TPB){
            int j = i & 4095; int k = j >> 4, b4 = j & 15;
            if (i < 4096) ((float4*)hs0)[j] = __ldcg((const float4*)&src0[k*BB + b0 + b4*4]);
            else          ((float4*)hs1)[j] = __ldcg((const float4*)&src1[k*BB + b0 + b4*4]);
        }
        // prefetch gi0 for GRU0 update
        float gir=0.f, giz=0.f, gin=0.f;
        if (t < 256 && ph < 512){
            const float* gb = g_gi0 + (size_t)ph*768*BB;
            gir = __ldcg(&gb[(size_t)u*BB       + b0 + bl]);
            giz = __ldcg(&gb[(size_t)(256+u)*BB + b0 + bl]);
            gin = __ldcg(&gb[(size_t)(512+u)*BB + b0 + bl]);
        }
        __syncthreads();

        // ------- fused 3-GEMM: 36 rows x 64 batch x 256 k -------------------
        if (w < 12){
            // rows 0..23 (hs0 source), 12 warps = 2 k-halves x 6 row-groups(4)
            const int kh = w / 6, rg = w - 6*(w/6);
            const float* hp = hs0 + kh*(128*64) + (l << 1);
            const float* wd = wAd + (rg*4)*512 + kh*256;
            unsigned long long a0=0ULL,a1=0ULL,a2=0ULL,a3=0ULL;
            #pragma unroll 8
            for (int k = 0; k < 128; k += 2){
                ulonglong2 w0 = *(const ulonglong2*)(wd + 2*k);
                ulonglong2 w1 = *(const ulonglong2*)(wd + 512  + 2*k);
                ulonglong2 w2 = *(const ulonglong2*)(wd + 1024 + 2*k);
                ulonglong2 w3 = *(const ulonglong2*)(wd + 1536 + 2*k);
                unsigned long long hA = *(const unsigned long long*)(hp + k*64);
                unsigned long long hB = *(const unsigned long long*)(hp + (k+1)*64);
                ffma2(a0, hA, w0.x); ffma2(a1, hA, w1.x);
                ffma2(a2, hA, w2.x); ffma2(a3, hA, w3.x);
                ffma2(a0, hB, w0.y); ffma2(a1, hB, w1.y);
                ffma2(a2, hB, w2.y); ffma2(a3, hB, w3.y);
            }
            float* pa = pA + (kh*24 + rg*4)*64 + (l << 1);
            *(float2*)&pa[0]   = u2f2(a0);
            *(float2*)&pa[64]  = u2f2(a1);
            *(float2*)&pa[128] = u2f2(a2);
            *(float2*)&pa[192] = u2f2(a3);
        } else {
            // rows 24..35 (hs1 source), 4 warps x 3 rows, full k=256
            const int rg = w - 12;
            const float* hp = hs1 + (l << 1);
            const float* wd = wAd + (24 + rg*3)*512;
            unsigned long long c0=0ULL,c1=0ULL,c2=0ULL;
            #pragma unroll 8
            for (int k = 0; k < 256; k += 2){
                ulonglong2 w0 = *(const ulonglong2*)(wd + 2*k);
                ulonglong2 w1 = *(const ulonglong2*)(wd + 512  + 2*k);
                ulonglong2 w2 = *(const ulonglong2*)(wd + 1024 + 2*k);
                unsigned long long hA = *(const unsigned long long*)(hp + k*64);
                unsigned long long hB = *(const unsigned long long*)(hp + (k+1)*64);
                ffma2(c0, hA, w0.x); ffma2(c1, hA, w1.x); ffma2(c2, hA, w2.x);
                ffma2(c0, hB, w0.y); ffma2(c1, hB, w1.y); ffma2(c2, hB, w2.y);
            }
            float* pc = pC + (rg*3)*64 + (l << 1);
            *(float2*)&pc[0]   = u2f2(c0);
            *(float2*)&pc[64]  = u2f2(c1);
            *(float2*)&pc[128] = u2f2(c2);
        }
        __syncthreads();

        // ------- elementwise updates (threads 0..255) ------------------------
        if (t < 256){
            int r0 = ui*3;
            if (ph < 512){
                // GRU0: h0_out[ph]
                float s0 = pA[r0*64+bl]     + pA[(24+r0)*64+bl];
                float s1 = pA[(r0+1)*64+bl] + pA[(24+r0+1)*64+bl];
                float s2 = pA[(r0+2)*64+bl] + pA[(24+r0+2)*64+bl];
                float r = sigmoidf_(gir + s0 + b0r);
                float z = sigmoidf_(giz + s1 + b0z);
                float n = tanhf(gin + r*(s2 + b0n));
                float hold = hs0[u*64 + bl];
                float hnew = (1.f - z)*n + z*hold;
                g_h0[ph & 1][u*BB + b0 + bl] = 0.1f*hold + 0.9f*hnew;
            }
            if (ph >= 1){
                // GRU1: h1_out[ph-1]
                int q0 = 12 + r0;
                float i0 = pA[q0*64+bl]     + pA[(24+q0)*64+bl]     + b1ir;
                float i1 = pA[(q0+1)*64+bl] + pA[(24+q0+1)*64+bl]   + b1iz;
                float i2 = pA[(q0+2)*64+bl] + pA[(24+q0+2)*64+bl]   + b1in;
                float hg0 = pC[r0*64+bl]     + b1hr;
                float hg1 = pC[(r0+1)*64+bl] + b1hz;
                float hg2 = pC[(r0+2)*64+bl] + b1hn;
                float r = sigmoidf_(i0 + hg0);
                float z = sigmoidf_(i1 + hg1);
                float n = tanhf(i2 + r*hg2);
                float hold = hs1[u*64 + bl];
                float hnew = (1.f - z)*n + z*hold;
                float hout = 0.1f*hold + 0.9f*hnew;
                g_h1[(ph+1) & 1][u*BB + b0 + bl] = hout;
                g_H[((size_t)(ph-1)*256 + u)*BB + b0 + bl] = hout;
            }
        }
        gbar((unsigned int)(ph+1));
    }
}

// ---------------- kernel 4: MDN head GEMM + epilogue (FFMA2) ----------------
__global__ __launch_bounds__(256) void out_gemm(const float* __restrict__ enc,
    const float* __restrict__ Wpi, const float* __restrict__ bpi,
    const float* __restrict__ Wsg, const float* __restrict__ bsg,
    const float* __restrict__ Wmu, const float* __restrict__ bmu,
    float* __restrict__ out)
{
    __shared__ float As[32][68];
    __shared__ float Wd[32][196];   // 96 cols duplicated
    __shared__ float Rs[64][96];
    const int s  = blockIdx.y;
    const int b0 = blockIdx.x * 64;
    const int t  = threadIdx.x;
    const int bg = t & 15, cg = t >> 4;
    unsigned long long acc[6][2];
    #pragma unroll
    for (int i = 0; i < 6; i++){ acc[i][0] = 0ULL; acc[i][1] = 0ULL; }

    for (int kk = 0; kk < 512; kk += 32){
        for (int i = t; i < 2048; i += 256){
            int k = i >> 6, b = i & 63;
            int kg = kk + k;
            float v;
            if (kg < 256) v = g_H[((size_t)s*256 + kg)*BB + b0 + b];
            else          v = enc[(((size_t)(b0+b))*SS + s)*CC + (kg-256)];
            As[k][b] = v;
        }
        for (int i = t; i < 32*96; i += 256){
            int k = i/96, c = i - k*96;
            int kg = kk + k;
            float v = 0.f;
            if      (c < 10) v = Wpi[(size_t)c*512 + kg];
            else if (c < 50) v = Wsg[(size_t)(c-10)*512 + kg];
            else if (c < 90) v = Wmu[(size_t)(c-50)*512 + kg];
            Wd[k][2*c]   = v;
            Wd[k][2*c+1] = v;
        }
        __syncthreads();
        #pragma unroll 4
        for (int k = 0; k < 32; k++){
            ulonglong2 a   = *(const ulonglong2*)&As[k][bg*4];
            ulonglong2 w01 = *(const ulonglong2*)&Wd[k][cg*12];
            ulonglong2 w23 = *(const ulonglong2*)&Wd[k][cg*12+4];
            ulonglong2 w45 = *(const ulonglong2*)&Wd[k][cg*12+8];
            ffma2(acc[0][0], a.x, w01.x); ffma2(acc[0][1], a.y, w01.x);
            ffma2(acc[1][0], a.x, w01.y); ffma2(acc[1][1], a.y, w01.y);
            ffma2(acc[2][0], a.x, w23.x); ffma2(acc[2][1], a.y, w23.x);
            ffma2(acc[3][0], a.x, w23.y); ffma2(acc[3][1], a.y, w23.y);
            ffma2(acc[4][0], a.x, w45.x); ffma2(acc[4][1], a.y, w45.x);
            ffma2(acc[5][0], a.x, w45.y); ffma2(acc[5][1], a.y, w45.y);
        }
        __syncthreads();
    }
    #pragma unroll
    for (int ci = 0; ci < 6; ci++){
        int c = cg*6 + ci;
        float bias = (c < 10) ? bpi[c] : (c < 50) ? bsg[c-10] : (c < 90) ? bmu[c-50] : 0.f;
        float2 p0 = u2f2(acc[ci][0]);
        float2 p1 = u2f2(acc[ci][1]);
        Rs[bg*4+0][c] = p0.x + bias;
        Rs[bg*4+1][c] = p0.y + bias;
        Rs[bg*4+2][c] = p1.x + bias;
        Rs[bg*4+3][c] = p1.y + bias;
    }
    __syncthreads();

    if (t < 64){
        int b = b0 + t;
        float lv[10]; float m = -1e30f;
        #pragma unroll
        for (int g = 0; g < 10; g++){ lv[g] = Rs[t][g]; m = fmaxf(m, lv[g]); }
        float sum = 0.f;
        #pragma unroll
        for (int g = 0; g < 10; g++){ lv[g] = expf(lv[g]-m); sum += lv[g]; }
        float inv = 1.f/sum;
        size_t base = (size_t)OUT_PI + ((size_t)b*SS + s)*10;
        #pragma unroll
        for (int g = 0; g < 10; g++) out[base + g] = lv[g]*inv;
    }
    for (int i = t; i < 64*40; i += 256){
        int row = i/40, j = i - row*40;
        int b = b0 + row;
        float x  = Rs[row][10+j];
        float xm = Rs[row][50+j];
        size_t base = ((size_t)b*SS + s)*40 + j;
        out[(size_t)OUT_SG + base] = (x > 0.f) ? (x + 1.f) : expf(x);
        out[(size_t)OUT_MU + base] = xm;
    }
}

// ---------------- kernel 5: tgt copy + duration mask ------------------------
__global__ void tail_kernel(const float* __restrict__ tgt,
                            const int* __restrict__ dur,
                            float* __restrict__ out){
    if (blockIdx.x < 1024){
        int idx = blockIdx.x*256 + threadIdx.x;
        out[idx] = tgt[idx];
    } else {
        int b = blockIdx.x - 1024;
        __shared__ int cnt;
        if (threadIdx.x == 0) cnt = 0;
        __syncthreads();
        int local = 0;
        for (int s = threadIdx.x; s < SS; s += 256) local += (dur[b*SS + s] > 0) ? 1 : 0;
        #pragma unroll
        for (int o = 16; o; o >>= 1) local += __shfl_down_sync(0xffffffffu, local, o);
        if ((threadIdx.x & 31) == 0) atomicAdd(&cnt, local);
        __syncthreads();
        int c = cnt;
        for (int s = threadIdx.x; s < SS; s += 256)
            out[OUT_MASK + b*SS + s] = (s >= c) ? 1.f : 0.f;
    }
}

// ---------------- launch -----------------------------------------------------
#define REC_SMEM ((36*512 + 16384*2 + 2*24*64 + 12*64) * (int)sizeof(float))

extern "C" void kernel_launch(void* const* d_in, const int* in_sizes, int n_in,
                              void* d_out, int out_size)
{
    const float* enc   = (const float*)d_in[0];
    const float* tgt   = (const float*)d_in[1];
    const int*   dur   = (const int*)  d_in[2];
    const float* W_pre = (const float*)d_in[3];
    const float* b_pre = (const float*)d_in[4];
    const float* Wih0  = (const float*)d_in[5];
    const float* Whh0  = (const float*)d_in[6];
    const float* bih0  = (const float*)d_in[7];
    const float* bhh0  = (const float*)d_in[8];
    const float* Wih1  = (const float*)d_in[9];
    const float* Whh1  = (const float*)d_in[10];
    const float* bih1  = (const float*)d_in[11];
    const float* bhh1  = (const float*)d_in[12];
    const float* Wpi   = (const float*)d_in[13];
    const float* bpi   = (const float*)d_in[14];
    const float* Wsg   = (const float*)d_in[15];
    const float* bsg   = (const float*)d_in[16];
    const float* Wmu   = (const float*)d_in[17];
    const float* bmu   = (const float*)d_in[18];
    float* out = (float*)d_out;

    init_kernel<<<128, 256>>>();

    prenet_kernel<<<(BB*SS*DOO + 255)/256, 256>>>(tgt, W_pre, b_pre);

    dim3 g2(2, 12, SS);
    gi0_gemm<<<g2, 256>>>(enc, Wih0, bih0);

    cudaFuncSetAttribute(rec_kernel, cudaFuncAttributeMaxDynamicSharedMemorySize, REC_SMEM);
    rec_kernel<<<NCTA, TPB, REC_SMEM>>>(Whh0, bhh0, Wih1, bih1, Whh1, bhh1);

    dim3 g4(2, SS);
    out_gemm<<<g4, 256>>>(enc, Wpi, bpi, Wsg, bsg, Wmu, bmu, out);

    tail_kernel<<<1024 + BB, 256>>>(tgt, dur, out);
}

// round 6
// speedup vs baseline: 1.3278x; 1.0858x over previous
#include <cuda_runtime.h>
#include <math.h>

#define BB   128
#define SS   512
#define CC   256
#define DOO  4
#define GG   10
#define NCTA 128
#define TPB  512

#define OUT_PI   (BB*SS*DOO)                    /* 262144  */
#define OUT_SG   (OUT_PI + BB*SS*GG)            /* 917504  */
#define OUT_MU   (OUT_SG + BB*SS*GG*DOO)        /* 3538944 */
#define OUT_MASK (OUT_MU + BB*SS*GG*DOO)        /* 6160384 */

// ---------------- scratch (static device globals; no cudaMalloc) ------------
__device__ float g_pn[BB*SS*DOO];                 // prenet output [b][s][d]
__device__ float g_gi0[(size_t)SS*768*BB];        // x@Wih0^T + bih0, layout [s][col][b]
__device__ float g_h0[2][256*BB];                 // h0 double buffer, [u][b]
__device__ float g_h1[2][256*BB];                 // h1 double buffer, [u][b]
__device__ float g_H[(size_t)SS*256*BB];          // h1 history, [s][u][b]
__device__ __align__(16) unsigned int g_arr[NCTA]; // contiguous arrive flags (4 lines)

__device__ __forceinline__ float sigmoidf_(float x){ return 1.f/(1.f + expf(-x)); }

__device__ __forceinline__ void ffma2(unsigned long long &acc,
                                      unsigned long long a, unsigned long long b){
    asm("fma.rn.f32x2 %0, %1, %2, %0;" : "+l"(acc) : "l"(a), "l"(b));
}
__device__ __forceinline__ float2 u2f2(unsigned long long v){
    float2 f; asm("mov.b64 {%0,%1}, %2;" : "=f"(f.x), "=f"(f.y) : "l"(v)); return f;
}

// all-peers grid barrier, compact flags: warp 0 polls 128 flags as 32 x v4 loads
__device__ __forceinline__ void gbar(unsigned int tgt){
    __syncthreads();
    if (threadIdx.x == 0){
        __threadfence();
        *(volatile unsigned int*)&g_arr[blockIdx.x] = tgt;
    }
    if (threadIdx.x < 32){
        const unsigned int* p = &g_arr[threadIdx.x*4];
        bool done;
        do {
            unsigned int a,b,c,d;
            asm volatile("ld.volatile.global.v4.u32 {%0,%1,%2,%3}, [%4];"
                         : "=r"(a), "=r"(b), "=r"(c), "=r"(d) : "l"(p));
            unsigned int m = min(min(a,b), min(c,d));
            done = __all_sync(0xffffffffu, m >= tgt);
        } while (!done);
        __threadfence();
    }
    __syncthreads();
}

// ---------------- kernel 0: per-launch state reset ---------------------------
__global__ void init_kernel(){
    int i = blockIdx.x*256 + threadIdx.x;   // grid 128*256 = 32768
    if (i < NCTA) g_arr[i] = 0u;
    g_h0[0][i] = 0.f; g_h0[1][i] = 0.f;
    g_h1[0][i] = 0.f; g_h1[1][i] = 0.f;
}

// ---------------- kernel 1: prenet = prev @ W_pre^T + b_pre -----------------
__global__ void prenet_kernel(const float* __restrict__ tgt,
                              const float* __restrict__ W_pre,
                              const float* __restrict__ b_pre){
    int idx = blockIdx.x*256 + threadIdx.x;
    if (idx >= BB*SS*DOO) return;
    int d = idx & 3;
    int s = (idx >> 2) & (SS-1);
    int b = idx >> 11;
    float v = b_pre[d];
    if (s > 0){
        const float* pv = tgt + ((size_t)(b*SS + s - 1))*DOO;
        #pragma unroll
        for (int e = 0; e < 4; e++) v += pv[e]*W_pre[d*DOO + e];
    }
    g_pn[idx] = v;
}

// ---------------- kernel 2: gi0 = xs @ Wih0^T + bih0 (FFMA2, coalesced) -----
__global__ __launch_bounds__(256) void gi0_gemm(const float* __restrict__ enc,
                                                const float* __restrict__ Wih0,
                                                const float* __restrict__ bih0){
    __shared__ float As[32][68];
    __shared__ float Wd[32][132];   // duplicated col pairs
    const int s  = blockIdx.z;
    const int c0 = blockIdx.y * 64;
    const int b0 = blockIdx.x * 64;
    const int t  = threadIdx.x;
    const int bg = t & 15, cg = t >> 4;
    unsigned long long acc[4][2];
    #pragma unroll
    for (int i = 0; i < 4; i++){ acc[i][0] = 0ULL; acc[i][1] = 0ULL; }

    for (int kk = 0; kk < 260; kk += 32){
        // A tile: coalesced float4 along k, transpose into As
        for (int i = t; i < 512; i += 256){
            int b = i >> 3, kq = i & 7;
            int kg = kk + kq*4;
            float4 v = make_float4(0.f,0.f,0.f,0.f);
            if (kg < 256)       v = *(const float4*)&enc[(((size_t)(b0+b))*SS + s)*CC + kg];
            else if (kg == 256) v = *(const float4*)&g_pn[(((size_t)(b0+b))*SS + s)*DOO];
            int k = kq*4;
            As[k][b] = v.x; As[k+1][b] = v.y; As[k+2][b] = v.z; As[k+3][b] = v.w;
        }
        // W tile: coalesced float4 along k, duplicated store
        for (int i = t; i < 512; i += 256){
            int c = i >> 3, kq = i & 7;
            int kg = kk + kq*4;
            float4 v = make_float4(0.f,0.f,0.f,0.f);
            if (kg <= 256) v = *(const float4*)&Wih0[(size_t)(c0+c)*260 + kg];
            int k = kq*4;
            Wd[k][2*c] = v.x;   Wd[k][2*c+1] = v.x;
            Wd[k+1][2*c] = v.y; Wd[k+1][2*c+1] = v.y;
            Wd[k+2][2*c] = v.z; Wd[k+2][2*c+1] = v.z;
            Wd[k+3][2*c] = v.w; Wd[k+3][2*c+1] = v.w;
        }
        __syncthreads();
        #pragma unroll 8
        for (int k = 0; k < 32; k++){
            ulonglong2 a   = *(const ulonglong2*)&As[k][bg*4];
            ulonglong2 w01 = *(const ulonglong2*)&Wd[k][cg*8];
            ulonglong2 w23 = *(const ulonglong2*)&Wd[k][cg*8+4];
            ffma2(acc[0][0], a.x, w01.x); ffma2(acc[0][1], a.y, w01.x);
            ffma2(acc[1][0], a.x, w01.y); ffma2(acc[1][1], a.y, w01.y);
            ffma2(acc[2][0], a.x, w23.x); ffma2(acc[2][1], a.y, w23.x);
            ffma2(acc[3][0], a.x, w23.y); ffma2(acc[3][1], a.y, w23.y);
        }
        __syncthreads();
    }
    #pragma unroll
    for (int ci = 0; ci < 4; ci++){
        int c = c0 + cg*4 + ci;
        float bias = bih0[c];
        float2 p0 = u2f2(acc[ci][0]);
        float2 p1 = u2f2(acc[ci][1]);
        float4 o = make_float4(p0.x+bias, p0.y+bias, p1.x+bias, p1.y+bias);
        *(float4*)&g_gi0[((size_t)s*768 + c)*BB + b0 + bg*4] = o;
    }
}

// ---------------- kernel 3: persistent GRU recurrence, 1 barrier/phase ------
// Phase ph (0..512): h0_out[ph] = GRU0(x[ph], h0_out[ph-1])          (ph<512)
//                    h1_out[ph-1] = GRU1(h0_out[ph-1], h1_out[ph-2]) (ph>=1)
// 128 CTAs = 64 unit-groups (4 units) x 2 batch-halves (64 batches), 512 thr.
// 36 gate-rows per CTA: rows 0-11 gh0(Whh0), 12-23 gi1(Wih1), 24-35 gh1(Whh1).
// Staging split: warps 0-11 stage hs0 (bar 1), warps 12-15 stage hs1 (bar 2).
__global__ void __launch_bounds__(TPB, 1) rec_kernel(
    const float* __restrict__ Whh0, const float* __restrict__ bhh0,
    const float* __restrict__ Wih1, const float* __restrict__ bih1,
    const float* __restrict__ Whh1, const float* __restrict__ bhh1)
{
    extern __shared__ float sm[];
    float* wAd = sm;                 // 36*512  : dup weight rows      (72 KB)
    float* hs0 = wAd + 36*512;       // 256*64  : h0_out[ph-1] staging (64 KB)
    float* hs1 = hs0 + 16384;        // 256*64  : h1_out[ph-2] staging (64 KB)
    float* pA  = hs1 + 16384;        // 2*24*64 : partials rows 0-23 (2 k-halves)
    float* pC  = pA + 3072;          // 12*64   : full sums rows 24-35

    const int t = threadIdx.x;
    const int w = t >> 5, l = t & 31;
    const int ug = blockIdx.x >> 1, bh = blockIdx.x & 1;
    const int u0 = ug*4, b0 = bh*64;

    // ---- load 36 weight rows (duplicated pairs for FFMA2), resident all run
    for (int i = t; i < 36*256; i += TPB){
        int row = i >> 8, k = i & 255;
        int g3 = row/12, rr = row - g3*12;
        int ui2 = rr/3, g = rr - ui2*3;
        const float* W = (g3 == 0) ? Whh0 : (g3 == 1) ? Wih1 : Whh1;
        float v = W[(size_t)(g*256 + u0 + ui2)*256 + k];
        wAd[row*512 + 2*k]   = v;
        wAd[row*512 + 2*k+1] = v;
    }

    // ---- per-thread update constants (threads 0..255: 4 units x 64 batches)
    const int ui = (t & 255) >> 6;
    const int bl = t & 63;
    const int u  = u0 + ui;
    float b0r=0,b0z=0,b0n=0,b1ir=0,b1iz=0,b1in=0,b1hr=0,b1hz=0,b1hn=0;
    if (t < 256){
        b0r=bhh0[u]; b0z=bhh0[256+u]; b0n=bhh0[512+u];
        b1ir=bih1[u]; b1iz=bih1[256+u]; b1in=bih1[512+u];
        b1hr=bhh1[u]; b1hz=bhh1[256+u]; b1hn=bhh1[512+u];
    }

    for (int ph = 0; ph < 513; ph++){
        const float* src0 = g_h0[(ph+1) & 1];
        const float* src1 = g_h1[ph & 1];

        // prefetch per-thread update inputs (overlaps with staging below)
        float gir=0.f, giz=0.f, gin=0.f, hold0=0.f, hold1=0.f;
        if (t < 256){
            hold0 = __ldcg(&src0[u*BB + b0 + bl]);
            hold1 = __ldcg(&src1[u*BB + b0 + bl]);
            if (ph < 512){
                const float* gb = g_gi0 + (size_t)ph*768*BB;
                gir = __ldcg(&gb[(size_t)u*BB       + b0 + bl]);
                giz = __ldcg(&gb[(size_t)(256+u)*BB + b0 + bl]);
                gin = __ldcg(&gb[(size_t)(512+u)*BB + b0 + bl]);
            }
        }

        if (w < 12){
            // ---- group A: stage hs0, then rows 0..23 --------------------
            for (int i = t; i < 4096; i += 384){
                int k = i >> 4, b4 = i & 15;
                ((float4*)hs0)[i] = __ldcg((const float4*)&src0[k*BB + b0 + b4*4]);
            }
            asm volatile("bar.sync 1, 384;" ::: "memory");

            const int kh = w / 6, rg = w - 6*(w/6);
            const float* hp = hs0 + kh*(128*64) + (l << 1);
            const float* wd = wAd + (rg*4)*512 + kh*256;
            unsigned long long a0=0ULL,a1=0ULL,a2=0ULL,a3=0ULL;
            #pragma unroll 8
            for (int k = 0; k < 128; k += 2){
                ulonglong2 w0 = *(const ulonglong2*)(wd + 2*k);
                ulonglong2 w1 = *(const ulonglong2*)(wd + 512  + 2*k);
                ulonglong2 w2 = *(const ulonglong2*)(wd + 1024 + 2*k);
                ulonglong2 w3 = *(const ulonglong2*)(wd + 1536 + 2*k);
                unsigned long long hA = *(const unsigned long long*)(hp + k*64);
                unsigned long long hB = *(const unsigned long long*)(hp + (k+1)*64);
                ffma2(a0, hA, w0.x); ffma2(a1, hA, w1.x);
                ffma2(a2, hA, w2.x); ffma2(a3, hA, w3.x);
                ffma2(a0, hB, w0.y); ffma2(a1, hB, w1.y);
                ffma2(a2, hB, w2.y); ffma2(a3, hB, w3.y);
            }
            float* pa = pA + (kh*24 + rg*4)*64 + (l << 1);
            *(float2*)&pa[0]   = u2f2(a0);
            *(float2*)&pa[64]  = u2f2(a1);
            *(float2*)&pa[128] = u2f2(a2);
            *(float2*)&pa[192] = u2f2(a3);
        } else {
            // ---- group B: stage hs1, then rows 24..35 (full k=256) ------
            for (int i = t - 384; i < 4096; i += 128){
                int k = i >> 4, b4 = i & 15;
                ((float4*)hs1)[i] = __ldcg((const float4*)&src1[k*BB + b0 + b4*4]);
            }
            asm volatile("bar.sync 2, 128;" ::: "memory");

            const int rg = w - 12;
            const float* hp = hs1 + (l << 1);
            const float* wd = wAd + (24 + rg*3)*512;
            unsigned long long c0=0ULL,c1=0ULL,c2=0ULL;
            #pragma unroll 8
            for (int k = 0; k < 256; k += 2){
                ulonglong2 w0 = *(const ulonglong2*)(wd + 2*k);
                ulonglong2 w1 = *(const ulonglong2*)(wd + 512  + 2*k);
                ulonglong2 w2 = *(const ulonglong2*)(wd + 1024 + 2*k);
                unsigned long long hA = *(const unsigned long long*)(hp + k*64);
                unsigned long long hB = *(const unsigned long long*)(hp + (k+1)*64);
                ffma2(c0, hA, w0.x); ffma2(c1, hA, w1.x); ffma2(c2, hA, w2.x);
                ffma2(c0, hB, w0.y); ffma2(c1, hB, w1.y); ffma2(c2, hB, w2.y);
            }
            float* pc = pC + (rg*3)*64 + (l << 1);
            *(float2*)&pc[0]   = u2f2(c0);
            *(float2*)&pc[64]  = u2f2(c1);
            *(float2*)&pc[128] = u2f2(c2);
        }
        __syncthreads();

        // ------- elementwise updates (threads 0..255) ------------------------
        if (t < 256){
            int r0 = ui*3;
            if (ph < 512){
                // GRU0: h0_out[ph]
                float s0 = pA[r0*64+bl]     + pA[(24+r0)*64+bl];
                float s1 = pA[(r0+1)*64+bl] + pA[(24+r0+1)*64+bl];
                float s2 = pA[(r0+2)*64+bl] + pA[(24+r0+2)*64+bl];
                float r = sigmoidf_(gir + s0 + b0r);
                float z = sigmoidf_(giz + s1 + b0z);
                float n = tanhf(gin + r*(s2 + b0n));
                float hnew = (1.f - z)*n + z*hold0;
                g_h0[ph & 1][u*BB + b0 + bl] = 0.1f*hold0 + 0.9f*hnew;
            }
            if (ph >= 1){
                // GRU1: h1_out[ph-1]
                int q0 = 12 + r0;
                float i0 = pA[q0*64+bl]     + pA[(24+q0)*64+bl]     + b1ir;
                float i1 = pA[(q0+1)*64+bl] + pA[(24+q0+1)*64+bl]   + b1iz;
                float i2 = pA[(q0+2)*64+bl] + pA[(24+q0+2)*64+bl]   + b1in;
                float hg0 = pC[r0*64+bl]     + b1hr;
                float hg1 = pC[(r0+1)*64+bl] + b1hz;
                float hg2 = pC[(r0+2)*64+bl] + b1hn;
                float r = sigmoidf_(i0 + hg0);
                float z = sigmoidf_(i1 + hg1);
                float n = tanhf(i2 + r*hg2);
                float hnew = (1.f - z)*n + z*hold1;
                float hout = 0.1f*hold1 + 0.9f*hnew;
                g_h1[(ph+1) & 1][u*BB + b0 + bl] = hout;
                g_H[((size_t)(ph-1)*256 + u)*BB + b0 + bl] = hout;
            }
        }
        gbar((unsigned int)(ph+1));
    }
}

// ---------------- kernel 4: MDN head GEMM + epilogue (FFMA2, coalesced) -----
__global__ __launch_bounds__(256) void out_gemm(const float* __restrict__ enc,
    const float* __restrict__ Wpi, const float* __restrict__ bpi,
    const float* __restrict__ Wsg, const float* __restrict__ bsg,
    const float* __restrict__ Wmu, const float* __restrict__ bmu,
    float* __restrict__ out)
{
    __shared__ float As[32][68];
    __shared__ float Wd[32][196];   // 96 cols duplicated
    __shared__ float Rs[64][96];
    const int s  = blockIdx.y;
    const int b0 = blockIdx.x * 64;
    const int t  = threadIdx.x;
    const int bg = t & 15, cg = t >> 4;
    unsigned long long acc[6][2];
    #pragma unroll
    for (int i = 0; i < 6; i++){ acc[i][0] = 0ULL; acc[i][1] = 0ULL; }

    for (int kk = 0; kk < 512; kk += 32){
        if (kk < 256){
            // g_H: contiguous in b already
            for (int i = t; i < 2048; i += 256){
                int k = i >> 6, b = i & 63;
                As[k][b] = g_H[((size_t)s*256 + kk + k)*BB + b0 + b];
            }
        } else {
            // enc: coalesced float4 along channel dim, transpose into As
            for (int i = t; i < 512; i += 256){
                int b = i >> 3, kq = i & 7;
                int kg = kk - 256 + kq*4;
                float4 v = *(const float4*)&enc[(((size_t)(b0+b))*SS + s)*CC + kg];
                int k = kq*4;
                As[k][b] = v.x; As[k+1][b] = v.y; As[k+2][b] = v.z; As[k+3][b] = v.w;
            }
        }
        // W: coalesced float4 along k, duplicated store
        for (int i = t; i < 768; i += 256){
            int c = i >> 3, kq = i & 7;
            int kg = kk + kq*4;
            float4 v = make_float4(0.f,0.f,0.f,0.f);
            if      (c < 10) v = *(const float4*)&Wpi[(size_t)c*512 + kg];
            else if (c < 50) v = *(const float4*)&Wsg[(size_t)(c-10)*512 + kg];
            else if (c < 90) v = *(const float4*)&Wmu[(size_t)(c-50)*512 + kg];
            int k = kq*4;
            Wd[k][2*c] = v.x;   Wd[k][2*c+1] = v.x;
            Wd[k+1][2*c] = v.y; Wd[k+1][2*c+1] = v.y;
            Wd[k+2][2*c] = v.z; Wd[k+2][2*c+1] = v.z;
            Wd[k+3][2*c] = v.w; Wd[k+3][2*c+1] = v.w;
        }
        __syncthreads();
        #pragma unroll 4
        for (int k = 0; k < 32; k++){
            ulonglong2 a   = *(const ulonglong2*)&As[k][bg*4];
            ulonglong2 w01 = *(const ulonglong2*)&Wd[k][cg*12];
            ulonglong2 w23 = *(const ulonglong2*)&Wd[k][cg*12+4];
            ulonglong2 w45 = *(const ulonglong2*)&Wd[k][cg*12+8];
            ffma2(acc[0][0], a.x, w01.x); ffma2(acc[0][1], a.y, w01.x);
            ffma2(acc[1][0], a.x, w01.y); ffma2(acc[1][1], a.y, w01.y);
            ffma2(acc[2][0], a.x, w23.x); ffma2(acc[2][1], a.y, w23.x);
            ffma2(acc[3][0], a.x, w23.y); ffma2(acc[3][1], a.y, w23.y);
            ffma2(acc[4][0], a.x, w45.x); ffma2(acc[4][1], a.y, w45.x);
            ffma2(acc[5][0], a.x, w45.y); ffma2(acc[5][1], a.y, w45.y);
        }
        __syncthreads();
    }
    #pragma unroll
    for (int ci = 0; ci < 6; ci++){
        int c = cg*6 + ci;
        float bias = (c < 10) ? bpi[c] : (c < 50) ? bsg[c-10] : (c < 90) ? bmu[c-50] : 0.f;
        float2 p0 = u2f2(acc[ci][0]);
        float2 p1 = u2f2(acc[ci][1]);
        Rs[bg*4+0][c] = p0.x + bias;
        Rs[bg*4+1][c] = p0.y + bias;
        Rs[bg*4+2][c] = p1.x + bias;
        Rs[bg*4+3][c] = p1.y + bias;
    }
    __syncthreads();

    if (t < 64){
        int b = b0 + t;
        float lv[10]; float m = -1e30f;
        #pragma unroll
        for (int g = 0; g < 10; g++){ lv[g] = Rs[t][g]; m = fmaxf(m, lv[g]); }
        float sum = 0.f;
        #pragma unroll
        for (int g = 0; g < 10; g++){ lv[g] = expf(lv[g]-m); sum += lv[g]; }
        float inv = 1.f/sum;
        size_t base = (size_t)OUT_PI + ((size_t)b*SS + s)*10;
        #pragma unroll
        for (int g = 0; g < 10; g++) out[base + g] = lv[g]*inv;
    }
    for (int i = t; i < 64*40; i += 256){
        int row = i/40, j = i - row*40;
        int b = b0 + row;
        float x  = Rs[row][10+j];
        float xm = Rs[row][50+j];
        size_t base = ((size_t)b*SS + s)*40 + j;
        out[(size_t)OUT_SG + base] = (x > 0.f) ? (x + 1.f) : expf(x);
        out[(size_t)OUT_MU + base] = xm;
    }
}

// ---------------- kernel 5: tgt copy + duration mask ------------------------
__global__ void tail_kernel(const float* __restrict__ tgt,
                            const int* __restrict__ dur,
                            float* __restrict__ out){
    if (blockIdx.x < 1024){
        int idx = blockIdx.x*256 + threadIdx.x;
        out[idx] = tgt[idx];
    } else {
        int b = blockIdx.x - 1024;
        __shared__ int cnt;
        if (threadIdx.x == 0) cnt = 0;
        __syncthreads();
        int local = 0;
        for (int s = threadIdx.x; s < SS; s += 256) local += (dur[b*SS + s] > 0) ? 1 : 0;
        #pragma unroll
        for (int o = 16; o; o >>= 1) local += __shfl_down_sync(0xffffffffu, local, o);
        if ((threadIdx.x & 31) == 0) atomicAdd(&cnt, local);
        __syncthreads();
        int c = cnt;
        for (int s = threadIdx.x; s < SS; s += 256)
            out[OUT_MASK + b*SS + s] = (s >= c) ? 1.f : 0.f;
    }
}

// ---------------- launch -----------------------------------------------------
#define REC_SMEM ((36*512 + 16384*2 + 2*24*64 + 12*64) * (int)sizeof(float))

extern "C" void kernel_launch(void* const* d_in, const int* in_sizes, int n_in,
                              void* d_out, int out_size)
{
    const float* enc   = (const float*)d_in[0];
    const float* tgt   = (const float*)d_in[1];
    const int*   dur   = (const int*)  d_in[2];
    const float* W_pre = (const float*)d_in[3];
    const float* b_pre = (const float*)d_in[4];
    const float* Wih0  = (const float*)d_in[5];
    const float* Whh0  = (const float*)d_in[6];
    const float* bih0  = (const float*)d_in[7];
    const float* bhh0  = (const float*)d_in[8];
    const float* Wih1  = (const float*)d_in[9];
    const float* Whh1  = (const float*)d_in[10];
    const float* bih1  = (const float*)d_in[11];
    const float* bhh1  = (const float*)d_in[12];
    const float* Wpi   = (const float*)d_in[13];
    const float* bpi   = (const float*)d_in[14];
    const float* Wsg   = (const float*)d_in[15];
    const float* bsg   = (const float*)d_in[16];
    const float* Wmu   = (const float*)d_in[17];
    const float* bmu   = (const float*)d_in[18];
    float* out = (float*)d_out;

    init_kernel<<<128, 256>>>();

    prenet_kernel<<<(BB*SS*DOO + 255)/256, 256>>>(tgt, W_pre, b_pre);

    dim3 g2(2, 12, SS);
    gi0_gemm<<<g2, 256>>>(enc, Wih0, bih0);

    cudaFuncSetAttribute(rec_kernel, cudaFuncAttributeMaxDynamicSharedMemorySize, REC_SMEM);
    rec_kernel<<<NCTA, TPB, REC_SMEM>>>(Whh0, bhh0, Wih1, bih1, Whh1, bhh1);

    dim3 g4(2, SS);
    out_gemm<<<g4, 256>>>(enc, Wpi, bpi, Wsg, bsg, Wmu, bmu, out);

    tail_kernel<<<1024 + BB, 256>>>(tgt, dur, out);
}

// round 7
// speedup vs baseline: 1.5476x; 1.1655x over previous
#include <cuda_runtime.h>
#include <math.h>

#define BB   128
#define SS   512
#define CC   256
#define DOO  4
#define GG   10
#define NCTA 128
#define TPB  512

#define OUT_PI   (BB*SS*DOO)                    /* 262144  */
#define OUT_SG   (OUT_PI + BB*SS*GG)            /* 917504  */
#define OUT_MU   (OUT_SG + BB*SS*GG*DOO)        /* 3538944 */
#define OUT_MASK (OUT_MU + BB*SS*GG*DOO)        /* 6160384 */

// ---------------- scratch (static device globals; no cudaMalloc) ------------
__device__ float g_pn[BB*SS*DOO];                 // prenet output [b][s][d]
__device__ float g_gi0[(size_t)SS*768*BB];        // x@Wih0^T + bih0, layout [s][col][b]
__device__ float g_h0[2][256*BB];                 // h0 double buffer, [u][b]
__device__ float g_h1[2][256*BB];                 // h1 double buffer, [u][b]
__device__ float g_H[(size_t)SS*256*BB];          // h1 history, [s][u][b]
__device__ __align__(16) unsigned int g_arr[NCTA]; // arrive flags: [bh*64 + ug]

__device__ __forceinline__ float sigmoidf_(float x){ return 1.f/(1.f + expf(-x)); }

__device__ __forceinline__ void ffma2(unsigned long long &acc,
                                      unsigned long long a, unsigned long long b){
    asm("fma.rn.f32x2 %0, %1, %2, %0;" : "+l"(acc) : "l"(a), "l"(b));
}
__device__ __forceinline__ float2 u2f2(unsigned long long v){
    float2 f; asm("mov.b64 {%0,%1}, %2;" : "=f"(f.x), "=f"(f.y) : "l"(v)); return f;
}

// per-batch-half grid barrier over 64 CTAs (halves are fully independent)
__device__ __forceinline__ void gbar(unsigned int tgt, int bh){
    __syncthreads();
    if (threadIdx.x == 0){
        __threadfence();
        *(volatile unsigned int*)&g_arr[(bh<<6) + (blockIdx.x>>1)] = tgt;
    }
    if (threadIdx.x < 32){
        const unsigned int* p = &g_arr[(bh<<6) + (threadIdx.x & 15)*4];
        bool done;
        do {
            unsigned int a,b,c,d;
            asm volatile("ld.volatile.global.v4.u32 {%0,%1,%2,%3}, [%4];"
                         : "=r"(a), "=r"(b), "=r"(c), "=r"(d) : "l"(p));
            unsigned int m = min(min(a,b), min(c,d));
            done = (threadIdx.x < 16) ? (m >= tgt) : true;
        } while (!__all_sync(0xffffffffu, done));
        __threadfence();
    }
    __syncthreads();
}

// ---------------- kernel 0: per-launch state reset ---------------------------
__global__ void init_kernel(){
    int i = blockIdx.x*256 + threadIdx.x;   // grid 128*256 = 32768
    if (i < NCTA) g_arr[i] = 0u;
    g_h0[0][i] = 0.f; g_h0[1][i] = 0.f;
    g_h1[0][i] = 0.f; g_h1[1][i] = 0.f;
}

// ---------------- kernel 1: prenet = prev @ W_pre^T + b_pre -----------------
__global__ void prenet_kernel(const float* __restrict__ tgt,
                              const float* __restrict__ W_pre,
                              const float* __restrict__ b_pre){
    int idx = blockIdx.x*256 + threadIdx.x;
    if (idx >= BB*SS*DOO) return;
    int d = idx & 3;
    int s = (idx >> 2) & (SS-1);
    int b = idx >> 11;
    float v = b_pre[d];
    if (s > 0){
        const float* pv = tgt + ((size_t)(b*SS + s - 1))*DOO;
        #pragma unroll
        for (int e = 0; e < 4; e++) v += pv[e]*W_pre[d*DOO + e];
    }
    g_pn[idx] = v;
}

// ---------------- kernel 2: gi0 = xs @ Wih0^T + bih0 (FFMA2, coalesced) -----
__global__ __launch_bounds__(256) void gi0_gemm(const float* __restrict__ enc,
                                                const float* __restrict__ Wih0,
                                                const float* __restrict__ bih0){
    __shared__ float As[32][68];
    __shared__ float Wd[32][132];
    const int s  = blockIdx.z;
    const int c0 = blockIdx.y * 64;
    const int b0 = blockIdx.x * 64;
    const int t  = threadIdx.x;
    const int bg = t & 15, cg = t >> 4;
    unsigned long long acc[4][2];
    #pragma unroll
    for (int i = 0; i < 4; i++){ acc[i][0] = 0ULL; acc[i][1] = 0ULL; }

    for (int kk = 0; kk < 260; kk += 32){
        for (int i = t; i < 512; i += 256){
            int b = i >> 3, kq = i & 7;
            int kg = kk + kq*4;
            float4 v = make_float4(0.f,0.f,0.f,0.f);
            if (kg < 256)       v = *(const float4*)&enc[(((size_t)(b0+b))*SS + s)*CC + kg];
            else if (kg == 256) v = *(const float4*)&g_pn[(((size_t)(b0+b))*SS + s)*DOO];
            int k = kq*4;
            As[k][b] = v.x; As[k+1][b] = v.y; As[k+2][b] = v.z; As[k+3][b] = v.w;
        }
        for (int i = t; i < 512; i += 256){
            int c = i >> 3, kq = i & 7;
            int kg = kk + kq*4;
            float4 v = make_float4(0.f,0.f,0.f,0.f);
            if (kg <= 256) v = *(const float4*)&Wih0[(size_t)(c0+c)*260 + kg];
            int k = kq*4;
            Wd[k][2*c] = v.x;   Wd[k][2*c+1] = v.x;
            Wd[k+1][2*c] = v.y; Wd[k+1][2*c+1] = v.y;
            Wd[k+2][2*c] = v.z; Wd[k+2][2*c+1] = v.z;
            Wd[k+3][2*c] = v.w; Wd[k+3][2*c+1] = v.w;
        }
        __syncthreads();
        #pragma unroll 8
        for (int k = 0; k < 32; k++){
            ulonglong2 a   = *(const ulonglong2*)&As[k][bg*4];
            ulonglong2 w01 = *(const ulonglong2*)&Wd[k][cg*8];
            ulonglong2 w23 = *(const ulonglong2*)&Wd[k][cg*8+4];
            ffma2(acc[0][0], a.x, w01.x); ffma2(acc[0][1], a.y, w01.x);
            ffma2(acc[1][0], a.x, w01.y); ffma2(acc[1][1], a.y, w01.y);
            ffma2(acc[2][0], a.x, w23.x); ffma2(acc[2][1], a.y, w23.x);
            ffma2(acc[3][0], a.x, w23.y); ffma2(acc[3][1], a.y, w23.y);
        }
        __syncthreads();
    }
    #pragma unroll
    for (int ci = 0; ci < 4; ci++){
        int c = c0 + cg*4 + ci;
        float bias = bih0[c];
        float2 p0 = u2f2(acc[ci][0]);
        float2 p1 = u2f2(acc[ci][1]);
        float4 o = make_float4(p0.x+bias, p0.y+bias, p1.x+bias, p1.y+bias);
        *(float4*)&g_gi0[((size_t)s*768 + c)*BB + b0 + bg*4] = o;
    }
}

// ---------------- kernel 3: persistent GRU recurrence -----------------------
// Phase ph (0..512): h0_out[ph] = GRU0(x[ph], h0_out[ph-1])          (ph<512)
//                    h1_out[ph-1] = GRU1(h0_out[ph-1], h1_out[ph-2]) (ph>=1)
// 128 CTAs = 64 unit-groups x 2 batch-halves, 512 thr.
// Rows 0-11 gh0(Whh0), 12-23 gi1(Wih1) [group A]; 24-35 gh1(Whh1) [group B].
// Group A: 12 warps = 4 k-quarters x 3 row-groups(8 rows), half-warp row split.
// Group B: 4 warps x 3 rows x full k=256.
__global__ void __launch_bounds__(TPB, 1) rec_kernel(
    const float* __restrict__ Whh0, const float* __restrict__ bhh0,
    const float* __restrict__ Wih1, const float* __restrict__ bih1,
    const float* __restrict__ Whh1, const float* __restrict__ bhh1)
{
    extern __shared__ float sm[];
    float* wqA = sm;                 // 3*4096  : A rows 0-23, quad-dup layout (48 KB)
    float* wBd = wqA + 12288;        // 12*512  : B rows dup pairs          (24 KB)
    float* hs0 = wBd + 6144;         // 256*64                                (64 KB)
    float* hs1 = hs0 + 16384;        // 256*64                                (64 KB)
    float* pA  = hs1 + 16384;        // 4*24*64 : A partials (4 k-quarters)   (24 KB)
    float* pC  = pA + 6144;          // 12*64   : B sums                       (3 KB)

    const int t = threadIdx.x;
    const int w = t >> 5, l = t & 31;
    const int ug = blockIdx.x >> 1, bh = blockIdx.x & 1;
    const int u0 = ug*4, b0 = bh*64;

    // ---- A weights (rows 0-23): [r3][k][16 floats: lo rows dup | hi rows dup]
    for (int i = t; i < 24*256; i += TPB){
        int row = i >> 8, k = i & 255;
        int g3 = row/12, rr = row - g3*12;
        int ui2 = rr/3, g = rr - ui2*3;
        const float* W = (g3 == 0) ? Whh0 : Wih1;
        float v = W[(size_t)(g*256 + u0 + ui2)*256 + k];
        int r3 = row >> 3, s = row & 7;
        int off = r3*4096 + k*16 + (s >> 2)*8 + (s & 3)*2;
        wqA[off] = v; wqA[off+1] = v;
    }
    // ---- B weights (rows 24-35): dup pairs
    for (int i = t; i < 12*256; i += TPB){
        int row = i >> 8, k = i & 255;
        int ui2 = row/3, g = row - ui2*3;
        float v = Whh1[(size_t)(g*256 + u0 + ui2)*256 + k];
        wBd[row*512 + 2*k]   = v;
        wBd[row*512 + 2*k+1] = v;
    }

    // ---- per-thread update constants (threads 0..255: 4 units x 64 batches)
    const int ui = (t & 255) >> 6;
    const int bl = t & 63;
    const int u  = u0 + ui;
    float b0r=0,b0z=0,b0n=0,b1ir=0,b1iz=0,b1in=0,b1hr=0,b1hz=0,b1hn=0;
    if (t < 256){
        b0r=bhh0[u]; b0z=bhh0[256+u]; b0n=bhh0[512+u];
        b1ir=bih1[u]; b1iz=bih1[256+u]; b1in=bih1[512+u];
        b1hr=bhh1[u]; b1hz=bhh1[256+u]; b1hn=bhh1[512+u];
    }

    float hout1 = 0.f;   // h1 output carried across barrier for deferred g_H store

    for (int ph = 0; ph < 513; ph++){
        const float* src0 = g_h0[(ph+1) & 1];
        const float* src1 = g_h1[ph & 1];

        // deferred g_H store from previous phase (off the fence critical path)
        if (t < 256 && ph >= 2)
            g_H[((size_t)(ph-2)*256 + u)*BB + b0 + bl] = hout1;

        // prefetch per-thread update inputs
        float gir=0.f, giz=0.f, gin=0.f, hold0=0.f, hold1=0.f;
        if (t < 256){
            hold0 = __ldcg(&src0[u*BB + b0 + bl]);
            hold1 = __ldcg(&src1[u*BB + b0 + bl]);
            if (ph < 512){
                const float* gb = g_gi0 + (size_t)ph*768*BB;
                gir = __ldcg(&gb[(size_t)u*BB       + b0 + bl]);
                giz = __ldcg(&gb[(size_t)(256+u)*BB + b0 + bl]);
                gin = __ldcg(&gb[(size_t)(512+u)*BB + b0 + bl]);
            }
        }

        if (w < 12){
            // ---- group A: stage hs0, then 8 rows x 64-k quarter ------------
            for (int i = t; i < 4096; i += 384){
                int k = i >> 4, b4 = i & 15;
                ((float4*)hs0)[i] = __ldcg((const float4*)&src0[k*BB + b0 + b4*4]);
            }
            asm volatile("bar.sync 1, 384;" ::: "memory");

            const int q = w & 3, r3 = w >> 2;      // k-quarter, row-group
            const int half = l >> 4, lb = l & 15;  // half-warp row split
            const float* hp = hs0 + q*4096 + lb*4;
            const float* wp = wqA + r3*4096 + q*1024 + half*8;
            unsigned long long a00=0,a01=0,a10=0,a11=0,a20=0,a21=0,a30=0,a31=0;
            #pragma unroll 4
            for (int k = 0; k < 64; k++){
                ulonglong2 hq = *(const ulonglong2*)(hp + k*64);
                ulonglong2 wA_ = *(const ulonglong2*)(wp + k*16);
                ulonglong2 wB_ = *(const ulonglong2*)(wp + k*16 + 4);
                ffma2(a00, hq.x, wA_.x); ffma2(a01, hq.y, wA_.x);
                ffma2(a10, hq.x, wA_.y); ffma2(a11, hq.y, wA_.y);
                ffma2(a20, hq.x, wB_.x); ffma2(a21, hq.y, wB_.x);
                ffma2(a30, hq.x, wB_.y); ffma2(a31, hq.y, wB_.y);
            }
            const int rowbase = q*24 + r3*8 + half*4;
            {
                float2 p0, p1;
                p0 = u2f2(a00); p1 = u2f2(a01);
                *(float4*)&pA[(rowbase+0)*64 + lb*4] = make_float4(p0.x,p0.y,p1.x,p1.y);
                p0 = u2f2(a10); p1 = u2f2(a11);
                *(float4*)&pA[(rowbase+1)*64 + lb*4] = make_float4(p0.x,p0.y,p1.x,p1.y);
                p0 = u2f2(a20); p1 = u2f2(a21);
                *(float4*)&pA[(rowbase+2)*64 + lb*4] = make_float4(p0.x,p0.y,p1.x,p1.y);
                p0 = u2f2(a30); p1 = u2f2(a31);
                *(float4*)&pA[(rowbase+3)*64 + lb*4] = make_float4(p0.x,p0.y,p1.x,p1.y);
            }
        } else {
            // ---- group B: stage hs1, then 3 rows x full k=256 --------------
            for (int i = t - 384; i < 4096; i += 128){
                int k = i >> 4, b4 = i & 15;
                ((float4*)hs1)[i] = __ldcg((const float4*)&src1[k*BB + b0 + b4*4]);
            }
            asm volatile("bar.sync 2, 128;" ::: "memory");

            const int rg = w - 12;
            const float* hp = hs1 + (l << 1);
            const float* wd = wBd + (rg*3)*512;
            unsigned long long c0=0ULL,c1=0ULL,c2=0ULL;
            #pragma unroll 8
            for (int k = 0; k < 256; k += 2){
                ulonglong2 w0 = *(const ulonglong2*)(wd + 2*k);
                ulonglong2 w1 = *(const ulonglong2*)(wd + 512  + 2*k);
                ulonglong2 w2 = *(const ulonglong2*)(wd + 1024 + 2*k);
                unsigned long long hA = *(const unsigned long long*)(hp + k*64);
                unsigned long long hB = *(const unsigned long long*)(hp + (k+1)*64);
                ffma2(c0, hA, w0.x); ffma2(c1, hA, w1.x); ffma2(c2, hA, w2.x);
                ffma2(c0, hB, w0.y); ffma2(c1, hB, w1.y); ffma2(c2, hB, w2.y);
            }
            float* pc = pC + (rg*3)*64 + (l << 1);
            *(float2*)&pc[0]   = u2f2(c0);
            *(float2*)&pc[64]  = u2f2(c1);
            *(float2*)&pc[128] = u2f2(c2);
        }
        __syncthreads();

        // ------- elementwise updates (threads 0..255) ------------------------
        if (t < 256){
            int r0 = ui*3;
            if (ph < 512){
                float s0 = pA[r0*64+bl]     + pA[(24+r0)*64+bl]     + pA[(48+r0)*64+bl]     + pA[(72+r0)*64+bl];
                float s1 = pA[(r0+1)*64+bl] + pA[(24+r0+1)*64+bl]   + pA[(48+r0+1)*64+bl]   + pA[(72+r0+1)*64+bl];
                float s2 = pA[(r0+2)*64+bl] + pA[(24+r0+2)*64+bl]   + pA[(48+r0+2)*64+bl]   + pA[(72+r0+2)*64+bl];
                float r = sigmoidf_(gir + s0 + b0r);
                float z = sigmoidf_(giz + s1 + b0z);
                float n = tanhf(gin + r*(s2 + b0n));
                float hnew = (1.f - z)*n + z*hold0;
                g_h0[ph & 1][u*BB + b0 + bl] = 0.1f*hold0 + 0.9f*hnew;
            }
            if (ph >= 1){
                int q0 = 12 + r0;
                float i0 = pA[q0*64+bl]     + pA[(24+q0)*64+bl]     + pA[(48+q0)*64+bl]     + pA[(72+q0)*64+bl]     + b1ir;
                float i1 = pA[(q0+1)*64+bl] + pA[(24+q0+1)*64+bl]   + pA[(48+q0+1)*64+bl]   + pA[(72+q0+1)*64+bl]   + b1iz;
                float i2 = pA[(q0+2)*64+bl] + pA[(24+q0+2)*64+bl]   + pA[(48+q0+2)*64+bl]   + pA[(72+q0+2)*64+bl]   + b1in;
                float hg0 = pC[r0*64+bl]     + b1hr;
                float hg1 = pC[(r0+1)*64+bl] + b1hz;
                float hg2 = pC[(r0+2)*64+bl] + b1hn;
                float r = sigmoidf_(i0 + hg0);
                float z = sigmoidf_(i1 + hg1);
                float n = tanhf(i2 + r*hg2);
                float hnew = (1.f - z)*n + z*hold1;
                hout1 = 0.1f*hold1 + 0.9f*hnew;
                g_h1[(ph+1) & 1][u*BB + b0 + bl] = hout1;
            }
        }
        gbar((unsigned int)(ph+1), bh);
    }
    // final deferred g_H store (step 511, computed at ph=512)
    if (t < 256)
        g_H[((size_t)511*256 + u)*BB + b0 + bl] = hout1;
}

// ---------------- kernel 4: MDN head GEMM + epilogue (FFMA2, coalesced) -----
__global__ __launch_bounds__(256) void out_gemm(const float* __restrict__ enc,
    const float* __restrict__ Wpi, const float* __restrict__ bpi,
    const float* __restrict__ Wsg, const float* __restrict__ bsg,
    const float* __restrict__ Wmu, const float* __restrict__ bmu,
    float* __restrict__ out)
{
    __shared__ float As[32][68];
    __shared__ float Wd[32][196];
    __shared__ float Rs[64][96];
    const int s  = blockIdx.y;
    const int b0 = blockIdx.x * 64;
    const int t  = threadIdx.x;
    const int bg = t & 15, cg = t >> 4;
    unsigned long long acc[6][2];
    #pragma unroll
    for (int i = 0; i < 6; i++){ acc[i][0] = 0ULL; acc[i][1] = 0ULL; }

    for (int kk = 0; kk < 512; kk += 32){
        if (kk < 256){
            for (int i = t; i < 2048; i += 256){
                int k = i >> 6, b = i & 63;
                As[k][b] = g_H[((size_t)s*256 + kk + k)*BB + b0 + b];
            }
        } else {
            for (int i = t; i < 512; i += 256){
                int b = i >> 3, kq = i & 7;
                int kg = kk - 256 + kq*4;
                float4 v = *(const float4*)&enc[(((size_t)(b0+b))*SS + s)*CC + kg];
                int k = kq*4;
                As[k][b] = v.x; As[k+1][b] = v.y; As[k+2][b] = v.z; As[k+3][b] = v.w;
            }
        }
        for (int i = t; i < 768; i += 256){
            int c = i >> 3, kq = i & 7;
            int kg = kk + kq*4;
            float4 v = make_float4(0.f,0.f,0.f,0.f);
            if      (c < 10) v = *(const float4*)&Wpi[(size_t)c*512 + kg];
            else if (c < 50) v = *(const float4*)&Wsg[(size_t)(c-10)*512 + kg];
            else if (c < 90) v = *(const float4*)&Wmu[(size_t)(c-50)*512 + kg];
            int k = kq*4;
            Wd[k][2*c] = v.x;   Wd[k][2*c+1] = v.x;
            Wd[k+1][2*c] = v.y; Wd[k+1][2*c+1] = v.y;
            Wd[k+2][2*c] = v.z; Wd[k+2][2*c+1] = v.z;
            Wd[k+3][2*c] = v.w; Wd[k+3][2*c+1] = v.w;
        }
        __syncthreads();
        #pragma unroll 4
        for (int k = 0; k < 32; k++){
            ulonglong2 a   = *(const ulonglong2*)&As[k][bg*4];
            ulonglong2 w01 = *(const ulonglong2*)&Wd[k][cg*12];
            ulonglong2 w23 = *(const ulonglong2*)&Wd[k][cg*12+4];
            ulonglong2 w45 = *(const ulonglong2*)&Wd[k][cg*12+8];
            ffma2(acc[0][0], a.x, w01.x); ffma2(acc[0][1], a.y, w01.x);
            ffma2(acc[1][0], a.x, w01.y); ffma2(acc[1][1], a.y, w01.y);
            ffma2(acc[2][0], a.x, w23.x); ffma2(acc[2][1], a.y, w23.x);
            ffma2(acc[3][0], a.x, w23.y); ffma2(acc[3][1], a.y, w23.y);
            ffma2(acc[4][0], a.x, w45.x); ffma2(acc[4][1], a.y, w45.x);
            ffma2(acc[5][0], a.x, w45.y); ffma2(acc[5][1], a.y, w45.y);
        }
        __syncthreads();
    }
    #pragma unroll
    for (int ci = 0; ci < 6; ci++){
        int c = cg*6 + ci;
        float bias = (c < 10) ? bpi[c] : (c < 50) ? bsg[c-10] : (c < 90) ? bmu[c-50] : 0.f;
        float2 p0 = u2f2(acc[ci][0]);
        float2 p1 = u2f2(acc[ci][1]);
        Rs[bg*4+0][c] = p0.x + bias;
        Rs[bg*4+1][c] = p0.y + bias;
        Rs[bg*4+2][c] = p1.x + bias;
        Rs[bg*4+3][c] = p1.y + bias;
    }
    __syncthreads();

    if (t < 64){
        int b = b0 + t;
        float lv[10]; float m = -1e30f;
        #pragma unroll
        for (int g = 0; g < 10; g++){ lv[g] = Rs[t][g]; m = fmaxf(m, lv[g]); }
        float sum = 0.f;
        #pragma unroll
        for (int g = 0; g < 10; g++){ lv[g] = expf(lv[g]-m); sum += lv[g]; }
        float inv = 1.f/sum;
        size_t base = (size_t)OUT_PI + ((size_t)b*SS + s)*10;
        #pragma unroll
        for (int g = 0; g < 10; g++) out[base + g] = lv[g]*inv;
    }
    for (int i = t; i < 64*40; i += 256){
        int row = i/40, j = i - row*40;
        int b = b0 + row;
        float x  = Rs[row][10+j];
        float xm = Rs[row][50+j];
        size_t base = ((size_t)b*SS + s)*40 + j;
        out[(size_t)OUT_SG + base] = (x > 0.f) ? (x + 1.f) : expf(x);
        out[(size_t)OUT_MU + base] = xm;
    }
}

// ---------------- kernel 5: tgt copy + duration mask ------------------------
__global__ void tail_kernel(const float* __restrict__ tgt,
                            const int* __restrict__ dur,
                            float* __restrict__ out){
    if (blockIdx.x < 1024){
        int idx = blockIdx.x*256 + threadIdx.x;
        out[idx] = tgt[idx];
    } else {
        int b = blockIdx.x - 1024;
        __shared__ int cnt;
        if (threadIdx.x == 0) cnt = 0;
        __syncthreads();
        int local = 0;
        for (int s = threadIdx.x; s < SS; s += 256) local += (dur[b*SS + s] > 0) ? 1 : 0;
        #pragma unroll
        for (int o = 16; o; o >>= 1) local += __shfl_down_sync(0xffffffffu, local, o);
        if ((threadIdx.x & 31) == 0) atomicAdd(&cnt, local);
        __syncthreads();
        int c = cnt;
        for (int s = threadIdx.x; s < SS; s += 256)
            out[OUT_MASK + b*SS + s] = (s >= c) ? 1.f : 0.f;
    }
}

// ---------------- launch -----------------------------------------------------
#define REC_SMEM ((12288 + 6144 + 16384 + 16384 + 6144 + 768) * (int)sizeof(float))

extern "C" void kernel_launch(void* const* d_in, const int* in_sizes, int n_in,
                              void* d_out, int out_size)
{
    const float* enc   = (const float*)d_in[0];
    const float* tgt   = (const float*)d_in[1];
    const int*   dur   = (const int*)  d_in[2];
    const float* W_pre = (const float*)d_in[3];
    const float* b_pre = (const float*)d_in[4];
    const float* Wih0  = (const float*)d_in[5];
    const float* Whh0  = (const float*)d_in[6];
    const float* bih0  = (const float*)d_in[7];
    const float* bhh0  = (const float*)d_in[8];
    const float* Wih1  = (const float*)d_in[9];
    const float* Whh1  = (const float*)d_in[10];
    const float* bih1  = (const float*)d_in[11];
    const float* bhh1  = (const float*)d_in[12];
    const float* Wpi   = (const float*)d_in[13];
    const float* bpi   = (const float*)d_in[14];
    const float* Wsg   = (const float*)d_in[15];
    const float* bsg   = (const float*)d_in[16];
    const float* Wmu   = (const float*)d_in[17];
    const float* bmu   = (const float*)d_in[18];
    float* out = (float*)d_out;

    init_kernel<<<128, 256>>>();

    prenet_kernel<<<(BB*SS*DOO + 255)/256, 256>>>(tgt, W_pre, b_pre);

    dim3 g2(2, 12, SS);
    gi0_gemm<<<g2, 256>>>(enc, Wih0, bih0);

    cudaFuncSetAttribute(rec_kernel, cudaFuncAttributeMaxDynamicSharedMemorySize, REC_SMEM);
    rec_kernel<<<NCTA, TPB, REC_SMEM>>>(Whh0, bhh0, Wih1, bih1, Whh1, bhh1);

    dim3 g4(2, SS);
    out_gemm<<<g4, 256>>>(enc, Wpi, bpi, Wsg, bsg, Wmu, bmu, out);

    tail_kernel<<<1024 + BB, 256>>>(tgt, dur, out);
}

// round 8
// speedup vs baseline: 1.6415x; 1.0607x over previous
#include <cuda_runtime.h>
#include <math.h>

#define BB   128
#define SS   512
#define CC   256
#define DOO  4
#define GG   10
#define NCTA 128
#define TPB  512

#define OUT_PI   (BB*SS*DOO)                    /* 262144  */
#define OUT_SG   (OUT_PI + BB*SS*GG)            /* 917504  */
#define OUT_MU   (OUT_SG + BB*SS*GG*DOO)        /* 3538944 */
#define OUT_MASK (OUT_MU + BB*SS*GG*DOO)        /* 6160384 */

// ---------------- scratch (static device globals; no cudaMalloc) ------------
__device__ float g_pn[BB*SS*DOO];                 // prenet output [b][s][d]
__device__ float g_gi0[(size_t)SS*768*BB];        // x@Wih0^T + bih0, layout [s][col][b]
__device__ float g_h0[2][256*BB];                 // h0 double buffer, [u][b]
__device__ float g_h1[2][256*BB];                 // h1 double buffer, [u][b]
__device__ float g_H[(size_t)SS*256*BB];          // h1 history, [s][u][b]
__device__ __align__(16) unsigned int g_arr[NCTA]; // arrive flags: [bh*64 + ug]

__device__ __forceinline__ float sigmoidf_(float x){ return 1.f/(1.f + expf(-x)); }

__device__ __forceinline__ void ffma2(unsigned long long &acc,
                                      unsigned long long a, unsigned long long b){
    asm("fma.rn.f32x2 %0, %1, %2, %0;" : "+l"(acc) : "l"(a), "l"(b));
}
__device__ __forceinline__ float2 u2f2(unsigned long long v){
    float2 f; asm("mov.b64 {%0,%1}, %2;" : "=f"(f.x), "=f"(f.y) : "l"(v)); return f;
}

// per-batch-half grid barrier over 64 CTAs (halves are fully independent)
__device__ __forceinline__ void gbar(unsigned int tgt, int bh){
    __syncthreads();
    if (threadIdx.x == 0){
        __threadfence();
        *(volatile unsigned int*)&g_arr[(bh<<6) + (blockIdx.x>>1)] = tgt;
    }
    if (threadIdx.x < 32){
        const unsigned int* p = &g_arr[(bh<<6) + (threadIdx.x & 15)*4];
        bool done;
        do {
            unsigned int a,b,c,d;
            asm volatile("ld.volatile.global.v4.u32 {%0,%1,%2,%3}, [%4];"
                         : "=r"(a), "=r"(b), "=r"(c), "=r"(d) : "l"(p));
            unsigned int m = min(min(a,b), min(c,d));
            done = (threadIdx.x < 16) ? (m >= tgt) : true;
        } while (!__all_sync(0xffffffffu, done));
        __threadfence();
    }
    __syncthreads();
}

// ---------------- kernel 0: per-launch state reset ---------------------------
__global__ void init_kernel(){
    int i = blockIdx.x*256 + threadIdx.x;   // grid 128*256 = 32768
    if (i < NCTA) g_arr[i] = 0u;
    g_h0[0][i] = 0.f; g_h0[1][i] = 0.f;
    g_h1[0][i] = 0.f; g_h1[1][i] = 0.f;
}

// ---------------- kernel 1: prenet = prev @ W_pre^T + b_pre -----------------
__global__ void prenet_kernel(const float* __restrict__ tgt,
                              const float* __restrict__ W_pre,
                              const float* __restrict__ b_pre){
    int idx = blockIdx.x*256 + threadIdx.x;
    if (idx >= BB*SS*DOO) return;
    int d = idx & 3;
    int s = (idx >> 2) & (SS-1);
    int b = idx >> 11;
    float v = b_pre[d];
    if (s > 0){
        const float* pv = tgt + ((size_t)(b*SS + s - 1))*DOO;
        #pragma unroll
        for (int e = 0; e < 4; e++) v += pv[e]*W_pre[d*DOO + e];
    }
    g_pn[idx] = v;
}

// ---------------- kernel 2: gi0 = xs @ Wih0^T + bih0 (FFMA2, coalesced) -----
__global__ __launch_bounds__(256) void gi0_gemm(const float* __restrict__ enc,
                                                const float* __restrict__ Wih0,
                                                const float* __restrict__ bih0){
    __shared__ float As[32][68];
    __shared__ float Wd[32][132];
    const int s  = blockIdx.z;
    const int c0 = blockIdx.y * 64;
    const int b0 = blockIdx.x * 64;
    const int t  = threadIdx.x;
    const int bg = t & 15, cg = t >> 4;
    unsigned long long acc[4][2];
    #pragma unroll
    for (int i = 0; i < 4; i++){ acc[i][0] = 0ULL; acc[i][1] = 0ULL; }

    for (int kk = 0; kk < 260; kk += 32){
        for (int i = t; i < 512; i += 256){
            int b = i >> 3, kq = i & 7;
            int kg = kk + kq*4;
            float4 v = make_float4(0.f,0.f,0.f,0.f);
            if (kg < 256)       v = *(const float4*)&enc[(((size_t)(b0+b))*SS + s)*CC + kg];
            else if (kg == 256) v = *(const float4*)&g_pn[(((size_t)(b0+b))*SS + s)*DOO];
            int k = kq*4;
            As[k][b] = v.x; As[k+1][b] = v.y; As[k+2][b] = v.z; As[k+3][b] = v.w;
        }
        for (int i = t; i < 512; i += 256){
            int c = i >> 3, kq = i & 7;
            int kg = kk + kq*4;
            float4 v = make_float4(0.f,0.f,0.f,0.f);
            if (kg <= 256) v = *(const float4*)&Wih0[(size_t)(c0+c)*260 + kg];
            int k = kq*4;
            Wd[k][2*c] = v.x;   Wd[k][2*c+1] = v.x;
            Wd[k+1][2*c] = v.y; Wd[k+1][2*c+1] = v.y;
            Wd[k+2][2*c] = v.z; Wd[k+2][2*c+1] = v.z;
            Wd[k+3][2*c] = v.w; Wd[k+3][2*c+1] = v.w;
        }
        __syncthreads();
        #pragma unroll 8
        for (int k = 0; k < 32; k++){
            ulonglong2 a   = *(const ulonglong2*)&As[k][bg*4];
            ulonglong2 w01 = *(const ulonglong2*)&Wd[k][cg*8];
            ulonglong2 w23 = *(const ulonglong2*)&Wd[k][cg*8+4];
            ffma2(acc[0][0], a.x, w01.x); ffma2(acc[0][1], a.y, w01.x);
            ffma2(acc[1][0], a.x, w01.y); ffma2(acc[1][1], a.y, w01.y);
            ffma2(acc[2][0], a.x, w23.x); ffma2(acc[2][1], a.y, w23.x);
            ffma2(acc[3][0], a.x, w23.y); ffma2(acc[3][1], a.y, w23.y);
        }
        __syncthreads();
    }
    #pragma unroll
    for (int ci = 0; ci < 4; ci++){
        int c = c0 + cg*4 + ci;
        float bias = bih0[c];
        float2 p0 = u2f2(acc[ci][0]);
        float2 p1 = u2f2(acc[ci][1]);
        float4 o = make_float4(p0.x+bias, p0.y+bias, p1.x+bias, p1.y+bias);
        *(float4*)&g_gi0[((size_t)s*768 + c)*BB + b0 + bg*4] = o;
    }
}

// ---------------- kernel 3: persistent GRU recurrence -----------------------
// Phase ph (0..512): h0_out[ph] = GRU0(x[ph], h0_out[ph-1])          (ph<512)
//                    h1_out[ph-1] = GRU1(h0_out[ph-1], h1_out[ph-2]) (ph>=1)
// 128 CTAs = 64 unit-groups x 2 batch-halves, 512 thr.
// Group A (warps 0-11): rows 0-11 gh0(Whh0) + 12-23 gi1(Wih1), hs0 source.
//   4 k-quarters x 3 row-groups(8 rows), half-warp row split. Each quarter
//   staged by its own 3 consumer warps (named barrier 1+q, 96 threads).
// Group B (warps 12-15): rows gh1(Whh1, 12 rows), hs1 source.
//   2 k-halves x 2 row-groups(6 rows), half-warp row split (3+3). Each half
//   staged by its 2 consumer warps (named barrier 5+hh, 64 thr). k-halves
//   reduced into single pC via named barrier 7.
__global__ void __launch_bounds__(TPB, 1) rec_kernel(
    const float* __restrict__ Whh0, const float* __restrict__ bhh0,
    const float* __restrict__ Wih1, const float* __restrict__ bih1,
    const float* __restrict__ Whh1, const float* __restrict__ bhh1)
{
    extern __shared__ float sm[];
    float* wqA = sm;                 // 3*4096  : A rows 0-23, quad-dup layout (48 KB)
    float* wBd = wqA + 12288;        // 12*512  : B rows dup pairs            (24 KB)
    float* hs0 = wBd + 6144;         // 256*64                                (64 KB)
    float* hs1 = hs0 + 16384;        // 256*64                                (64 KB)
    float* pA  = hs1 + 16384;        // 4*24*64 : A partials (4 k-quarters)   (24 KB)
    float* pC  = pA + 6144;          // 12*64   : B sums (after reduce)        (3 KB)

    const int t = threadIdx.x;
    const int w = t >> 5, l = t & 31;
    const int ug = blockIdx.x >> 1, bh = blockIdx.x & 1;
    const int u0 = ug*4, b0 = bh*64;

    // ---- A weights (rows 0-23): [r3][k][16 floats: lo rows dup | hi rows dup]
    for (int i = t; i < 24*256; i += TPB){
        int row = i >> 8, k = i & 255;
        int g3 = row/12, rr = row - g3*12;
        int ui2 = rr/3, g = rr - ui2*3;
        const float* W = (g3 == 0) ? Whh0 : Wih1;
        float v = W[(size_t)(g*256 + u0 + ui2)*256 + k];
        int r3 = row >> 3, s = row & 7;
        int off = r3*4096 + k*16 + (s >> 2)*8 + (s & 3)*2;
        wqA[off] = v; wqA[off+1] = v;
    }
    // ---- B weights (rows 24-35): dup pairs along k
    for (int i = t; i < 12*256; i += TPB){
        int row = i >> 8, k = i & 255;
        int ui2 = row/3, g = row - ui2*3;
        float v = Whh1[(size_t)(g*256 + u0 + ui2)*256 + k];
        wBd[row*512 + 2*k]   = v;
        wBd[row*512 + 2*k+1] = v;
    }

    // ---- per-thread update constants (threads 0..255: 4 units x 64 batches)
    const int ui = (t & 255) >> 6;
    const int bl = t & 63;
    const int u  = u0 + ui;
    float b0r=0,b0z=0,b0n=0,b1ir=0,b1iz=0,b1in=0,b1hr=0,b1hz=0,b1hn=0;
    if (t < 256){
        b0r=bhh0[u]; b0z=bhh0[256+u]; b0n=bhh0[512+u];
        b1ir=bih1[u]; b1iz=bih1[256+u]; b1in=bih1[512+u];
        b1hr=bhh1[u]; b1hz=bhh1[256+u]; b1hn=bhh1[512+u];
    }

    float hout1 = 0.f;   // h1 output carried for deferred g_H store

    for (int ph = 0; ph < 513; ph++){
        const float* src0 = g_h0[(ph+1) & 1];
        const float* src1 = g_h1[ph & 1];

        // deferred g_H store from previous phase
        if (t < 256 && ph >= 2)
            g_H[((size_t)(ph-2)*256 + u)*BB + b0 + bl] = hout1;

        // prefetch per-thread update inputs
        float gir=0.f, giz=0.f, gin=0.f, hold0=0.f, hold1=0.f;
        if (t < 256){
            hold0 = __ldcg(&src0[u*BB + b0 + bl]);
            hold1 = __ldcg(&src1[u*BB + b0 + bl]);
            if (ph < 512){
                const float* gb = g_gi0 + (size_t)ph*768*BB;
                gir = __ldcg(&gb[(size_t)u*BB       + b0 + bl]);
                giz = __ldcg(&gb[(size_t)(256+u)*BB + b0 + bl]);
                gin = __ldcg(&gb[(size_t)(512+u)*BB + b0 + bl]);
            }
        }

        if (w < 12){
            const int q = w & 3, r3 = w >> 2;      // k-quarter, row-group
            // ---- stage hs0 quarter q (3 warps: q, q+4, q+8) ----------------
            for (int i = (r3 << 5) + l; i < 1024; i += 96){
                ((float4*)hs0)[(q << 10) + i] =
                    __ldcg((const float4*)&src0[((q << 6) + (i >> 4))*BB + b0 + (i & 15)*4]);
            }
            asm volatile("bar.sync %0, 96;" :: "r"(1 + q) : "memory");

            const int half = l >> 4, lb = l & 15;  // half-warp row split
            const float* hp = hs0 + q*4096 + lb*4;
            const float* wp = wqA + r3*4096 + q*1024 + half*8;
            unsigned long long a00=0,a01=0,a10=0,a11=0,a20=0,a21=0,a30=0,a31=0;
            #pragma unroll 4
            for (int k = 0; k < 64; k++){
                ulonglong2 hq = *(const ulonglong2*)(hp + k*64);
                ulonglong2 wA_ = *(const ulonglong2*)(wp + k*16);
                ulonglong2 wB_ = *(const ulonglong2*)(wp + k*16 + 4);
                ffma2(a00, hq.x, wA_.x); ffma2(a01, hq.y, wA_.x);
                ffma2(a10, hq.x, wA_.y); ffma2(a11, hq.y, wA_.y);
                ffma2(a20, hq.x, wB_.x); ffma2(a21, hq.y, wB_.x);
                ffma2(a30, hq.x, wB_.y); ffma2(a31, hq.y, wB_.y);
            }
            const int rowbase = q*24 + r3*8 + half*4;
            {
                float2 p0, p1;
                p0 = u2f2(a00); p1 = u2f2(a01);
                *(float4*)&pA[(rowbase+0)*64 + lb*4] = make_float4(p0.x,p0.y,p1.x,p1.y);
                p0 = u2f2(a10); p1 = u2f2(a11);
                *(float4*)&pA[(rowbase+1)*64 + lb*4] = make_float4(p0.x,p0.y,p1.x,p1.y);
                p0 = u2f2(a20); p1 = u2f2(a21);
                *(float4*)&pA[(rowbase+2)*64 + lb*4] = make_float4(p0.x,p0.y,p1.x,p1.y);
                p0 = u2f2(a30); p1 = u2f2(a31);
                *(float4*)&pA[(rowbase+3)*64 + lb*4] = make_float4(p0.x,p0.y,p1.x,p1.y);
            }
        } else {
            const int q2 = w - 12;                 // 0..3
            const int hh = q2 >> 1, rg = q2 & 1;   // k-half, row-group
            // ---- stage hs1 half hh (2 warps) -------------------------------
            for (int i = ((w & 1) << 5) + l; i < 2048; i += 64){
                ((float4*)hs1)[(hh << 11) + i] =
                    __ldcg((const float4*)&src1[((hh << 7) + (i >> 4))*BB + b0 + (i & 15)*4]);
            }
            asm volatile("bar.sync %0, 64;" :: "r"(5 + hh) : "memory");

            const int half = l >> 4, lb = l & 15;  // 3+3 row split
            const int rbase = rg*6 + half*3;
            const float* hp = hs1 + hh*(128*64) + lb*4;
            const float* wd = wBd + rbase*512 + hh*256;
            unsigned long long c00=0,c01=0,c10=0,c11=0,c20=0,c21=0;
            #pragma unroll 8
            for (int k2 = 0; k2 < 128; k2 += 2){
                ulonglong2 w0 = *(const ulonglong2*)(wd + 2*k2);
                ulonglong2 w1 = *(const ulonglong2*)(wd + 512  + 2*k2);
                ulonglong2 w2 = *(const ulonglong2*)(wd + 1024 + 2*k2);
                ulonglong2 hq0 = *(const ulonglong2*)(hp + k2*64);
                ulonglong2 hq1 = *(const ulonglong2*)(hp + (k2+1)*64);
                ffma2(c00, hq0.x, w0.x); ffma2(c01, hq0.y, w0.x);
                ffma2(c10, hq0.x, w1.x); ffma2(c11, hq0.y, w1.x);
                ffma2(c20, hq0.x, w2.x); ffma2(c21, hq0.y, w2.x);
                ffma2(c00, hq1.x, w0.y); ffma2(c01, hq1.y, w0.y);
                ffma2(c10, hq1.x, w1.y); ffma2(c11, hq1.y, w1.y);
                ffma2(c20, hq1.x, w2.y); ffma2(c21, hq1.y, w2.y);
            }
            if (hh == 0){
                float2 p0, p1;
                p0 = u2f2(c00); p1 = u2f2(c01);
                *(float4*)&pC[(rbase+0)*64 + lb*4] = make_float4(p0.x,p0.y,p1.x,p1.y);
                p0 = u2f2(c10); p1 = u2f2(c11);
                *(float4*)&pC[(rbase+1)*64 + lb*4] = make_float4(p0.x,p0.y,p1.x,p1.y);
                p0 = u2f2(c20); p1 = u2f2(c21);
                *(float4*)&pC[(rbase+2)*64 + lb*4] = make_float4(p0.x,p0.y,p1.x,p1.y);
            }
            asm volatile("bar.sync 7, 128;" ::: "memory");
            if (hh == 1){
                float2 p0, p1;
                float4 pr;
                p0 = u2f2(c00); p1 = u2f2(c01);
                pr = *(const float4*)&pC[(rbase+0)*64 + lb*4];
                *(float4*)&pC[(rbase+0)*64 + lb*4] =
                    make_float4(pr.x+p0.x, pr.y+p0.y, pr.z+p1.x, pr.w+p1.y);
                p0 = u2f2(c10); p1 = u2f2(c11);
                pr = *(const float4*)&pC[(rbase+1)*64 + lb*4];
                *(float4*)&pC[(rbase+1)*64 + lb*4] =
                    make_float4(pr.x+p0.x, pr.y+p0.y, pr.z+p1.x, pr.w+p1.y);
                p0 = u2f2(c20); p1 = u2f2(c21);
                pr = *(const float4*)&pC[(rbase+2)*64 + lb*4];
                *(float4*)&pC[(rbase+2)*64 + lb*4] =
                    make_float4(pr.x+p0.x, pr.y+p0.y, pr.z+p1.x, pr.w+p1.y);
            }
        }
        __syncthreads();

        // ------- elementwise updates (threads 0..255) ------------------------
        if (t < 256){
            int r0 = ui*3;
            if (ph < 512){
                float s0 = pA[r0*64+bl]     + pA[(24+r0)*64+bl]     + pA[(48+r0)*64+bl]     + pA[(72+r0)*64+bl];
                float s1 = pA[(r0+1)*64+bl] + pA[(24+r0+1)*64+bl]   + pA[(48+r0+1)*64+bl]   + pA[(72+r0+1)*64+bl];
                float s2 = pA[(r0+2)*64+bl] + pA[(24+r0+2)*64+bl]   + pA[(48+r0+2)*64+bl]   + pA[(72+r0+2)*64+bl];
                float r = sigmoidf_(gir + s0 + b0r);
                float z = sigmoidf_(giz + s1 + b0z);
                float n = tanhf(gin + r*(s2 + b0n));
                float hnew = (1.f - z)*n + z*hold0;
                g_h0[ph & 1][u*BB + b0 + bl] = 0.1f*hold0 + 0.9f*hnew;
            }
            if (ph >= 1){
                int q0 = 12 + r0;
                float i0 = pA[q0*64+bl]     + pA[(24+q0)*64+bl]     + pA[(48+q0)*64+bl]     + pA[(72+q0)*64+bl]     + b1ir;
                float i1 = pA[(q0+1)*64+bl] + pA[(24+q0+1)*64+bl]   + pA[(48+q0+1)*64+bl]   + pA[(72+q0+1)*64+bl]   + b1iz;
                float i2 = pA[(q0+2)*64+bl] + pA[(24+q0+2)*64+bl]   + pA[(48+q0+2)*64+bl]   + pA[(72+q0+2)*64+bl]   + b1in;
                float hg0 = pC[r0*64+bl]     + b1hr;
                float hg1 = pC[(r0+1)*64+bl] + b1hz;
                float hg2 = pC[(r0+2)*64+bl] + b1hn;
                float r = sigmoidf_(i0 + hg0);
                float z = sigmoidf_(i1 + hg1);
                float n = tanhf(i2 + r*hg2);
                float hnew = (1.f - z)*n + z*hold1;
                hout1 = 0.1f*hold1 + 0.9f*hnew;
                g_h1[(ph+1) & 1][u*BB + b0 + bl] = hout1;
            }
        }
        gbar((unsigned int)(ph+1), bh);
    }
    // final deferred g_H store (step 511, computed at ph=512)
    if (t < 256)
        g_H[((size_t)511*256 + u)*BB + b0 + bl] = hout1;
}

// ---------------- kernel 4: MDN head GEMM + epilogue (FFMA2, coalesced) -----
__global__ __launch_bounds__(256) void out_gemm(const float* __restrict__ enc,
    const float* __restrict__ Wpi, const float* __restrict__ bpi,
    const float* __restrict__ Wsg, const float* __restrict__ bsg,
    const float* __restrict__ Wmu, const float* __restrict__ bmu,
    float* __restrict__ out)
{
    __shared__ float As[32][68];
    __shared__ float Wd[32][196];
    __shared__ float Rs[64][96];
    const int s  = blockIdx.y;
    const int b0 = blockIdx.x * 64;
    const int t  = threadIdx.x;
    const int bg = t & 15, cg = t >> 4;
    unsigned long long acc[6][2];
    #pragma unroll
    for (int i = 0; i < 6; i++){ acc[i][0] = 0ULL; acc[i][1] = 0ULL; }

    for (int kk = 0; kk < 512; kk += 32){
        if (kk < 256){
            for (int i = t; i < 2048; i += 256){
                int k = i >> 6, b = i & 63;
                As[k][b] = g_H[((size_t)s*256 + kk + k)*BB + b0 + b];
            }
        } else {
            for (int i = t; i < 512; i += 256){
                int b = i >> 3, kq = i & 7;
                int kg = kk - 256 + kq*4;
                float4 v = *(const float4*)&enc[(((size_t)(b0+b))*SS + s)*CC + kg];
                int k = kq*4;
                As[k][b] = v.x; As[k+1][b] = v.y; As[k+2][b] = v.z; As[k+3][b] = v.w;
            }
        }
        for (int i = t; i < 768; i += 256){
            int c = i >> 3, kq = i & 7;
            int kg = kk + kq*4;
            float4 v = make_float4(0.f,0.f,0.f,0.f);
            if      (c < 10) v = *(const float4*)&Wpi[(size_t)c*512 + kg];
            else if (c < 50) v = *(const float4*)&Wsg[(size_t)(c-10)*512 + kg];
            else if (c < 90) v = *(const float4*)&Wmu[(size_t)(c-50)*512 + kg];
            int k = kq*4;
            Wd[k][2*c] = v.x;   Wd[k][2*c+1] = v.x;
            Wd[k+1][2*c] = v.y; Wd[k+1][2*c+1] = v.y;
            Wd[k+2][2*c] = v.z; Wd[k+2][2*c+1] = v.z;
            Wd[k+3][2*c] = v.w; Wd[k+3][2*c+1] = v.w;
        }
        __syncthreads();
        #pragma unroll 4
        for (int k = 0; k < 32; k++){
            ulonglong2 a   = *(const ulonglong2*)&As[k][bg*4];
            ulonglong2 w01 = *(const ulonglong2*)&Wd[k][cg*12];
            ulonglong2 w23 = *(const ulonglong2*)&Wd[k][cg*12+4];
            ulonglong2 w45 = *(const ulonglong2*)&Wd[k][cg*12+8];
            ffma2(acc[0][0], a.x, w01.x); ffma2(acc[0][1], a.y, w01.x);
            ffma2(acc[1][0], a.x, w01.y); ffma2(acc[1][1], a.y, w01.y);
            ffma2(acc[2][0], a.x, w23.x); ffma2(acc[2][1], a.y, w23.x);
            ffma2(acc[3][0], a.x, w23.y); ffma2(acc[3][1], a.y, w23.y);
            ffma2(acc[4][0], a.x, w45.x); ffma2(acc[4][1], a.y, w45.x);
            ffma2(acc[5][0], a.x, w45.y); ffma2(acc[5][1], a.y, w45.y);
        }
        __syncthreads();
    }
    #pragma unroll
    for (int ci = 0; ci < 6; ci++){
        int c = cg*6 + ci;
        float bias = (c < 10) ? bpi[c] : (c < 50) ? bsg[c-10] : (c < 90) ? bmu[c-50] : 0.f;
        float2 p0 = u2f2(acc[ci][0]);
        float2 p1 = u2f2(acc[ci][1]);
        Rs[bg*4+0][c] = p0.x + bias;
        Rs[bg*4+1][c] = p0.y + bias;
        Rs[bg*4+2][c] = p1.x + bias;
        Rs[bg*4+3][c] = p1.y + bias;
    }
    __syncthreads();

    if (t < 64){
        int b = b0 + t;
        float lv[10]; float m = -1e30f;
        #pragma unroll
        for (int g = 0; g < 10; g++){ lv[g] = Rs[t][g]; m = fmaxf(m, lv[g]); }
        float sum = 0.f;
        #pragma unroll
        for (int g = 0; g < 10; g++){ lv[g] = expf(lv[g]-m); sum += lv[g]; }
        float inv = 1.f/sum;
        size_t base = (size_t)OUT_PI + ((size_t)b*SS + s)*10;
        #pragma unroll
        for (int g = 0; g < 10; g++) out[base + g] = lv[g]*inv;
    }
    for (int i = t; i < 64*40; i += 256){
        int row = i/40, j = i - row*40;
        int b = b0 + row;
        float x  = Rs[row][10+j];
        float xm = Rs[row][50+j];
        size_t base = ((size_t)b*SS + s)*40 + j;
        out[(size_t)OUT_SG + base] = (x > 0.f) ? (x + 1.f) : expf(x);
        out[(size_t)OUT_MU + base] = xm;
    }
}

// ---------------- kernel 5: tgt copy + duration mask ------------------------
__global__ void tail_kernel(const float* __restrict__ tgt,
                            const int* __restrict__ dur,
                            float* __restrict__ out){
    if (blockIdx.x < 1024){
        int idx = blockIdx.x*256 + threadIdx.x;
        out[idx] = tgt[idx];
    } else {
        int b = blockIdx.x - 1024;
        __shared__ int cnt;
        if (threadIdx.x == 0) cnt = 0;
        __syncthreads();
        int local = 0;
        for (int s = threadIdx.x; s < SS; s += 256) local += (dur[b*SS + s] > 0) ? 1 : 0;
        #pragma unroll
        for (int o = 16; o; o >>= 1) local += __shfl_down_sync(0xffffffffu, local, o);
        if ((threadIdx.x & 31) == 0) atomicAdd(&cnt, local);
        __syncthreads();
        int c = cnt;
        for (int s = threadIdx.x; s < SS; s += 256)
            out[OUT_MASK + b*SS + s] = (s >= c) ? 1.f : 0.f;
    }
}

// ---------------- launch -----------------------------------------------------
#define REC_SMEM ((12288 + 6144 + 16384 + 16384 + 6144 + 768) * (int)sizeof(float))

extern "C" void kernel_launch(void* const* d_in, const int* in_sizes, int n_in,
                              void* d_out, int out_size)
{
    const float* enc   = (const float*)d_in[0];
    const float* tgt   = (const float*)d_in[1];
    const int*   dur   = (const int*)  d_in[2];
    const float* W_pre = (const float*)d_in[3];
    const float* b_pre = (const float*)d_in[4];
    const float* Wih0  = (const float*)d_in[5];
    const float* Whh0  = (const float*)d_in[6];
    const float* bih0  = (const float*)d_in[7];
    const float* bhh0  = (const float*)d_in[8];
    const float* Wih1  = (const float*)d_in[9];
    const float* Whh1  = (const float*)d_in[10];
    const float* bih1  = (const float*)d_in[11];
    const float* bhh1  = (const float*)d_in[12];
    const float* Wpi   = (const float*)d_in[13];
    const float* bpi   = (const float*)d_in[14];
    const float* Wsg   = (const float*)d_in[15];
    const float* bsg   = (const float*)d_in[16];
    const float* Wmu   = (const float*)d_in[17];
    const float* bmu   = (const float*)d_in[18];
    float* out = (float*)d_out;

    init_kernel<<<128, 256>>>();

    prenet_kernel<<<(BB*SS*DOO + 255)/256, 256>>>(tgt, W_pre, b_pre);

    dim3 g2(2, 12, SS);
    gi0_gemm<<<g2, 256>>>(enc, Wih0, bih0);

    cudaFuncSetAttribute(rec_kernel, cudaFuncAttributeMaxDynamicSharedMemorySize, REC_SMEM);
    rec_kernel<<<NCTA, TPB, REC_SMEM>>>(Whh0, bhh0, Wih1, bih1, Whh1, bhh1);

    dim3 g4(2, SS);
    out_gemm<<<g4, 256>>>(enc, Wpi, bpi, Wsg, bsg, Wmu, bmu, out);

    tail_kernel<<<1024 + BB, 256>>>(tgt, dur, out);
}

// round 9
// speedup vs baseline: 1.6421x; 1.0004x over previous
#include <cuda_runtime.h>
#include <math.h>

#define BB   128
#define SS   512
#define CC   256
#define DOO  4
#define GG   10
#define NCTA 128
#define TPB  512

#define OUT_PI   (BB*SS*DOO)                    /* 262144  */
#define OUT_SG   (OUT_PI + BB*SS*GG)            /* 917504  */
#define OUT_MU   (OUT_SG + BB*SS*GG*DOO)        /* 3538944 */
#define OUT_MASK (OUT_MU + BB*SS*GG*DOO)        /* 6160384 */

// ---------------- scratch (static device globals; no cudaMalloc) ------------
__device__ float g_pn[BB*SS*DOO];                 // prenet output [b][s][d]
__device__ float g_gi0[(size_t)SS*768*BB];        // x@Wih0^T + bih0, layout [s][col][b]
__device__ float g_h0[2][256*BB];                 // h0 double buffer, [u][b]
__device__ float g_h1[2][256*BB];                 // h1 double buffer, [u][b]
__device__ float g_H[(size_t)SS*256*BB];          // h1 history, [s][u][b]
__device__ __align__(16) unsigned int g_arr[NCTA]; // arrive flags: [bh*64 + ug]

__device__ __forceinline__ float sigmoidf_(float x){ return 1.f/(1.f + expf(-x)); }

__device__ __forceinline__ void ffma2(unsigned long long &acc,
                                      unsigned long long a, unsigned long long b){
    asm("fma.rn.f32x2 %0, %1, %2, %0;" : "+l"(acc) : "l"(a), "l"(b));
}
__device__ __forceinline__ float2 u2f2(unsigned long long v){
    float2 f; asm("mov.b64 {%0,%1}, %2;" : "=f"(f.x), "=f"(f.y) : "l"(v)); return f;
}

// per-batch-half grid barrier over 64 CTAs (halves are fully independent)
__device__ __forceinline__ void gbar(unsigned int tgt, int bh){
    __syncthreads();
    if (threadIdx.x == 0){
        __threadfence();
        *(volatile unsigned int*)&g_arr[(bh<<6) + (blockIdx.x>>1)] = tgt;
    }
    if (threadIdx.x < 32){
        const unsigned int* p = &g_arr[(bh<<6) + (threadIdx.x & 15)*4];
        bool done;
        do {
            unsigned int a,b,c,d;
            asm volatile("ld.volatile.global.v4.u32 {%0,%1,%2,%3}, [%4];"
                         : "=r"(a), "=r"(b), "=r"(c), "=r"(d) : "l"(p));
            unsigned int m = min(min(a,b), min(c,d));
            done = (threadIdx.x < 16) ? (m >= tgt) : true;
        } while (!__all_sync(0xffffffffu, done));
        __threadfence();
    }
    __syncthreads();
}

// ---------------- kernel 0: per-launch state reset ---------------------------
__global__ void init_kernel(){
    int i = blockIdx.x*256 + threadIdx.x;   // grid 128*256 = 32768
    if (i < NCTA) g_arr[i] = 0u;
    g_h0[0][i] = 0.f; g_h0[1][i] = 0.f;
    g_h1[0][i] = 0.f; g_h1[1][i] = 0.f;
}

// ---------------- kernel 1: prenet = prev @ W_pre^T + b_pre -----------------
__global__ void prenet_kernel(const float* __restrict__ tgt,
                              const float* __restrict__ W_pre,
                              const float* __restrict__ b_pre){
    int idx = blockIdx.x*256 + threadIdx.x;
    if (idx >= BB*SS*DOO) return;
    int d = idx & 3;
    int s = (idx >> 2) & (SS-1);
    int b = idx >> 11;
    float v = b_pre[d];
    if (s > 0){
        const float* pv = tgt + ((size_t)(b*SS + s - 1))*DOO;
        #pragma unroll
        for (int e = 0; e < 4; e++) v += pv[e]*W_pre[d*DOO + e];
    }
    g_pn[idx] = v;
}

// ---------------- kernel 2: gi0 = xs @ Wih0^T + bih0 (FFMA2, coalesced) -----
__global__ __launch_bounds__(256) void gi0_gemm(const float* __restrict__ enc,
                                                const float* __restrict__ Wih0,
                                                const float* __restrict__ bih0){
    __shared__ float As[32][68];
    __shared__ float Wd[32][132];
    const int s  = blockIdx.z;
    const int c0 = blockIdx.y * 64;
    const int b0 = blockIdx.x * 64;
    const int t  = threadIdx.x;
    const int bg = t & 15, cg = t >> 4;
    unsigned long long acc[4][2];
    #pragma unroll
    for (int i = 0; i < 4; i++){ acc[i][0] = 0ULL; acc[i][1] = 0ULL; }

    for (int kk = 0; kk < 260; kk += 32){
        for (int i = t; i < 512; i += 256){
            int b = i >> 3, kq = i & 7;
            int kg = kk + kq*4;
            float4 v = make_float4(0.f,0.f,0.f,0.f);
            if (kg < 256)       v = *(const float4*)&enc[(((size_t)(b0+b))*SS + s)*CC + kg];
            else if (kg == 256) v = *(const float4*)&g_pn[(((size_t)(b0+b))*SS + s)*DOO];
            int k = kq*4;
            As[k][b] = v.x; As[k+1][b] = v.y; As[k+2][b] = v.z; As[k+3][b] = v.w;
        }
        for (int i = t; i < 512; i += 256){
            int c = i >> 3, kq = i & 7;
            int kg = kk + kq*4;
            float4 v = make_float4(0.f,0.f,0.f,0.f);
            if (kg <= 256) v = *(const float4*)&Wih0[(size_t)(c0+c)*260 + kg];
            int k = kq*4;
            Wd[k][2*c] = v.x;   Wd[k][2*c+1] = v.x;
            Wd[k+1][2*c] = v.y; Wd[k+1][2*c+1] = v.y;
            Wd[k+2][2*c] = v.z; Wd[k+2][2*c+1] = v.z;
            Wd[k+3][2*c] = v.w; Wd[k+3][2*c+1] = v.w;
        }
        __syncthreads();
        #pragma unroll 8
        for (int k = 0; k < 32; k++){
            ulonglong2 a   = *(const ulonglong2*)&As[k][bg*4];
            ulonglong2 w01 = *(const ulonglong2*)&Wd[k][cg*8];
            ulonglong2 w23 = *(const ulonglong2*)&Wd[k][cg*8+4];
            ffma2(acc[0][0], a.x, w01.x); ffma2(acc[0][1], a.y, w01.x);
            ffma2(acc[1][0], a.x, w01.y); ffma2(acc[1][1], a.y, w01.y);
            ffma2(acc[2][0], a.x, w23.x); ffma2(acc[2][1], a.y, w23.x);
            ffma2(acc[3][0], a.x, w23.y); ffma2(acc[3][1], a.y, w23.y);
        }
        __syncthreads();
    }
    #pragma unroll
    for (int ci = 0; ci < 4; ci++){
        int c = c0 + cg*4 + ci;
        float bias = bih0[c];
        float2 p0 = u2f2(acc[ci][0]);
        float2 p1 = u2f2(acc[ci][1]);
        float4 o = make_float4(p0.x+bias, p0.y+bias, p1.x+bias, p1.y+bias);
        *(float4*)&g_gi0[((size_t)s*768 + c)*BB + b0 + bg*4] = o;
    }
}

// ---------------- kernel 3: persistent GRU recurrence -----------------------
// Phase ph (0..512): h0_out[ph] = GRU0(x[ph], h0_out[ph-1])          (ph<512)
//                    h1_out[ph-1] = GRU1(h0_out[ph-1], h1_out[ph-2]) (ph>=1)
// 128 CTAs = 64 unit-groups x 2 batch-halves, 512 thr.
// Group A (warps 0-11): rows 0-11 gh0(Whh0) + 12-23 gi1(Wih1), hs0 source.
//   4 k-quarters x 3 row-groups(8 rows), half-warp row split. Each quarter
//   staged by its own 3 consumer warps (named barrier 1+q, 96 threads).
// Group B (warps 12-15): rows gh1(Whh1, 12 rows), hs1 source.
//   2 k-halves x 2 row-groups(6 rows), half-warp row split (3+3). Each half
//   staged by its 2 consumer warps (named barrier 5+hh, 64 thr). k-halves
//   reduced into single pC via named barrier 7.
__global__ void __launch_bounds__(TPB, 1) rec_kernel(
    const float* __restrict__ Whh0, const float* __restrict__ bhh0,
    const float* __restrict__ Wih1, const float* __restrict__ bih1,
    const float* __restrict__ Whh1, const float* __restrict__ bhh1)
{
    extern __shared__ float sm[];
    float* wqA = sm;                 // 3*4096  : A rows 0-23, quad-dup layout (48 KB)
    float* wBd = wqA + 12288;        // 12*512  : B rows dup pairs            (24 KB)
    float* hs0 = wBd + 6144;         // 256*64                                (64 KB)
    float* hs1 = hs0 + 16384;        // 256*64                                (64 KB)
    float* pA  = hs1 + 16384;        // 4*24*64 : A partials (4 k-quarters)   (24 KB)
    float* pC  = pA + 6144;          // 12*64   : B sums (after reduce)        (3 KB)

    const int t = threadIdx.x;
    const int w = t >> 5, l = t & 31;
    const int ug = blockIdx.x >> 1, bh = blockIdx.x & 1;
    const int u0 = ug*4, b0 = bh*64;

    // ---- A weights (rows 0-23): [r3][k][16 floats: lo rows dup | hi rows dup]
    for (int i = t; i < 24*256; i += TPB){
        int row = i >> 8, k = i & 255;
        int g3 = row/12, rr = row - g3*12;
        int ui2 = rr/3, g = rr - ui2*3;
        const float* W = (g3 == 0) ? Whh0 : Wih1;
        float v = W[(size_t)(g*256 + u0 + ui2)*256 + k];
        int r3 = row >> 3, s = row & 7;
        int off = r3*4096 + k*16 + (s >> 2)*8 + (s & 3)*2;
        wqA[off] = v; wqA[off+1] = v;
    }
    // ---- B weights (rows 24-35): dup pairs along k
    for (int i = t; i < 12*256; i += TPB){
        int row = i >> 8, k = i & 255;
        int ui2 = row/3, g = row - ui2*3;
        float v = Whh1[(size_t)(g*256 + u0 + ui2)*256 + k];
        wBd[row*512 + 2*k]   = v;
        wBd[row*512 + 2*k+1] = v;
    }

    // ---- per-thread update constants (threads 0..255: 4 units x 64 batches)
    const int ui = (t & 255) >> 6;
    const int bl = t & 63;
    const int u  = u0 + ui;
    float b0r=0,b0z=0,b0n=0,b1ir=0,b1iz=0,b1in=0,b1hr=0,b1hz=0,b1hn=0;
    if (t < 256){
        b0r=bhh0[u]; b0z=bhh0[256+u]; b0n=bhh0[512+u];
        b1ir=bih1[u]; b1iz=bih1[256+u]; b1in=bih1[512+u];
        b1hr=bhh1[u]; b1hz=bhh1[256+u]; b1hn=bhh1[512+u];
    }

    float hout1 = 0.f;   // h1 output carried for deferred g_H store

    for (int ph = 0; ph < 513; ph++){
        const float* src0 = g_h0[(ph+1) & 1];
        const float* src1 = g_h1[ph & 1];

        // deferred g_H store from previous phase
        if (t < 256 && ph >= 2)
            g_H[((size_t)(ph-2)*256 + u)*BB + b0 + bl] = hout1;

        // prefetch per-thread update inputs
        float gir=0.f, giz=0.f, gin=0.f, hold0=0.f, hold1=0.f;
        if (t < 256){
            hold0 = __ldcg(&src0[u*BB + b0 + bl]);
            hold1 = __ldcg(&src1[u*BB + b0 + bl]);
            if (ph < 512){
                const float* gb = g_gi0 + (size_t)ph*768*BB;
                gir = __ldcg(&gb[(size_t)u*BB       + b0 + bl]);
                giz = __ldcg(&gb[(size_t)(256+u)*BB + b0 + bl]);
                gin = __ldcg(&gb[(size_t)(512+u)*BB + b0 + bl]);
            }
        }

        if (w < 12){
            const int q = w & 3, r3 = w >> 2;      // k-quarter, row-group
            // ---- stage hs0 quarter q (3 warps: q, q+4, q+8) ----------------
            for (int i = (r3 << 5) + l; i < 1024; i += 96){
                ((float4*)hs0)[(q << 10) + i] =
                    __ldcg((const float4*)&src0[((q << 6) + (i >> 4))*BB + b0 + (i & 15)*4]);
            }
            asm volatile("bar.sync %0, 96;" :: "r"(1 + q) : "memory");

            const int half = l >> 4, lb = l & 15;  // half-warp row split
            const float* hp = hs0 + q*4096 + lb*4;
            const float* wp = wqA + r3*4096 + q*1024 + half*8;
            unsigned long long a00=0,a01=0,a10=0,a11=0,a20=0,a21=0,a30=0,a31=0;
            #pragma unroll 4
            for (int k = 0; k < 64; k++){
                ulonglong2 hq = *(const ulonglong2*)(hp + k*64);
                ulonglong2 wA_ = *(const ulonglong2*)(wp + k*16);
                ulonglong2 wB_ = *(const ulonglong2*)(wp + k*16 + 4);
                ffma2(a00, hq.x, wA_.x); ffma2(a01, hq.y, wA_.x);
                ffma2(a10, hq.x, wA_.y); ffma2(a11, hq.y, wA_.y);
                ffma2(a20, hq.x, wB_.x); ffma2(a21, hq.y, wB_.x);
                ffma2(a30, hq.x, wB_.y); ffma2(a31, hq.y, wB_.y);
            }
            const int rowbase = q*24 + r3*8 + half*4;
            {
                float2 p0, p1;
                p0 = u2f2(a00); p1 = u2f2(a01);
                *(float4*)&pA[(rowbase+0)*64 + lb*4] = make_float4(p0.x,p0.y,p1.x,p1.y);
                p0 = u2f2(a10); p1 = u2f2(a11);
                *(float4*)&pA[(rowbase+1)*64 + lb*4] = make_float4(p0.x,p0.y,p1.x,p1.y);
                p0 = u2f2(a20); p1 = u2f2(a21);
                *(float4*)&pA[(rowbase+2)*64 + lb*4] = make_float4(p0.x,p0.y,p1.x,p1.y);
                p0 = u2f2(a30); p1 = u2f2(a31);
                *(float4*)&pA[(rowbase+3)*64 + lb*4] = make_float4(p0.x,p0.y,p1.x,p1.y);
            }
        } else {
            const int q2 = w - 12;                 // 0..3
            const int hh = q2 >> 1, rg = q2 & 1;   // k-half, row-group
            // ---- stage hs1 half hh (2 warps) -------------------------------
            for (int i = ((w & 1) << 5) + l; i < 2048; i += 64){
                ((float4*)hs1)[(hh << 11) + i] =
                    __ldcg((const float4*)&src1[((hh << 7) + (i >> 4))*BB + b0 + (i & 15)*4]);
            }
            asm volatile("bar.sync %0, 64;" :: "r"(5 + hh) : "memory");

            const int half = l >> 4, lb = l & 15;  // 3+3 row split
            const int rbase = rg*6 + half*3;
            const float* hp = hs1 + hh*(128*64) + lb*4;
            const float* wd = wBd + rbase*512 + hh*256;
            unsigned long long c00=0,c01=0,c10=0,c11=0,c20=0,c21=0;
            #pragma unroll 8
            for (int k2 = 0; k2 < 128; k2 += 2){
                ulonglong2 w0 = *(const ulonglong2*)(wd + 2*k2);
                ulonglong2 w1 = *(const ulonglong2*)(wd + 512  + 2*k2);
                ulonglong2 w2 = *(const ulonglong2*)(wd + 1024 + 2*k2);
                ulonglong2 hq0 = *(const ulonglong2*)(hp + k2*64);
                ulonglong2 hq1 = *(const ulonglong2*)(hp + (k2+1)*64);
                ffma2(c00, hq0.x, w0.x); ffma2(c01, hq0.y, w0.x);
                ffma2(c10, hq0.x, w1.x); ffma2(c11, hq0.y, w1.x);
                ffma2(c20, hq0.x, w2.x); ffma2(c21, hq0.y, w2.x);
                ffma2(c00, hq1.x, w0.y); ffma2(c01, hq1.y, w0.y);
                ffma2(c10, hq1.x, w1.y); ffma2(c11, hq1.y, w1.y);
                ffma2(c20, hq1.x, w2.y); ffma2(c21, hq1.y, w2.y);
            }
            if (hh == 0){
                float2 p0, p1;
                p0 = u2f2(c00); p1 = u2f2(c01);
                *(float4*)&pC[(rbase+0)*64 + lb*4] = make_float4(p0.x,p0.y,p1.x,p1.y);
                p0 = u2f2(c10); p1 = u2f2(c11);
                *(float4*)&pC[(rbase+1)*64 + lb*4] = make_float4(p0.x,p0.y,p1.x,p1.y);
                p0 = u2f2(c20); p1 = u2f2(c21);
                *(float4*)&pC[(rbase+2)*64 + lb*4] = make_float4(p0.x,p0.y,p1.x,p1.y);
            }
            asm volatile("bar.sync 7, 128;" ::: "memory");
            if (hh == 1){
                float2 p0, p1;
                float4 pr;
                p0 = u2f2(c00); p1 = u2f2(c01);
                pr = *(const float4*)&pC[(rbase+0)*64 + lb*4];
                *(float4*)&pC[(rbase+0)*64 + lb*4] =
                    make_float4(pr.x+p0.x, pr.y+p0.y, pr.z+p1.x, pr.w+p1.y);
                p0 = u2f2(c10); p1 = u2f2(c11);
                pr = *(const float4*)&pC[(rbase+1)*64 + lb*4];
                *(float4*)&pC[(rbase+1)*64 + lb*4] =
                    make_float4(pr.x+p0.x, pr.y+p0.y, pr.z+p1.x, pr.w+p1.y);
                p0 = u2f2(c20); p1 = u2f2(c21);
                pr = *(const float4*)&pC[(rbase+2)*64 + lb*4];
                *(float4*)&pC[(rbase+2)*64 + lb*4] =
                    make_float4(pr.x+p0.x, pr.y+p0.y, pr.z+p1.x, pr.w+p1.y);
            }
        }
        __syncthreads();

        // ------- elementwise updates (threads 0..255) ------------------------
        if (t < 256){
            int r0 = ui*3;
            if (ph < 512){
                float s0 = pA[r0*64+bl]     + pA[(24+r0)*64+bl]     + pA[(48+r0)*64+bl]     + pA[(72+r0)*64+bl];
                float s1 = pA[(r0+1)*64+bl] + pA[(24+r0+1)*64+bl]   + pA[(48+r0+1)*64+bl]   + pA[(72+r0+1)*64+bl];
                float s2 = pA[(r0+2)*64+bl] + pA[(24+r0+2)*64+bl]   + pA[(48+r0+2)*64+bl]   + pA[(72+r0+2)*64+bl];
                float r = sigmoidf_(gir + s0 + b0r);
                float z = sigmoidf_(giz + s1 + b0z);
                float n = tanhf(gin + r*(s2 + b0n));
                float hnew = (1.f - z)*n + z*hold0;
                g_h0[ph & 1][u*BB + b0 + bl] = 0.1f*hold0 + 0.9f*hnew;
            }
            if (ph >= 1){
                int q0 = 12 + r0;
                float i0 = pA[q0*64+bl]     + pA[(24+q0)*64+bl]     + pA[(48+q0)*64+bl]     + pA[(72+q0)*64+bl]     + b1ir;
                float i1 = pA[(q0+1)*64+bl] + pA[(24+q0+1)*64+bl]   + pA[(48+q0+1)*64+bl]   + pA[(72+q0+1)*64+bl]   + b1iz;
                float i2 = pA[(q0+2)*64+bl] + pA[(24+q0+2)*64+bl]   + pA[(48+q0+2)*64+bl]   + pA[(72+q0+2)*64+bl]   + b1in;
                float hg0 = pC[r0*64+bl]     + b1hr;
                float hg1 = pC[(r0+1)*64+bl] + b1hz;
                float hg2 = pC[(r0+2)*64+bl] + b1hn;
                float r = sigmoidf_(i0 + hg0);
                float z = sigmoidf_(i1 + hg1);
                float n = tanhf(i2 + r*hg2);
                float hnew = (1.f - z)*n + z*hold1;
                hout1 = 0.1f*hold1 + 0.9f*hnew;
                g_h1[(ph+1) & 1][u*BB + b0 + bl] = hout1;
            }
        }
        gbar((unsigned int)(ph+1), bh);
    }
    // final deferred g_H store (step 511, computed at ph=512)
    if (t < 256)
        g_H[((size_t)511*256 + u)*BB + b0 + bl] = hout1;
}

// ---------------- kernel 4: MDN head GEMM + epilogue (FFMA2, coalesced) -----
__global__ __launch_bounds__(256) void out_gemm(const float* __restrict__ enc,
    const float* __restrict__ Wpi, const float* __restrict__ bpi,
    const float* __restrict__ Wsg, const float* __restrict__ bsg,
    const float* __restrict__ Wmu, const float* __restrict__ bmu,
    float* __restrict__ out)
{
    __shared__ float As[32][68];
    __shared__ float Wd[32][196];
    __shared__ float Rs[64][96];
    const int s  = blockIdx.y;
    const int b0 = blockIdx.x * 64;
    const int t  = threadIdx.x;
    const int bg = t & 15, cg = t >> 4;
    unsigned long long acc[6][2];
    #pragma unroll
    for (int i = 0; i < 6; i++){ acc[i][0] = 0ULL; acc[i][1] = 0ULL; }

    for (int kk = 0; kk < 512; kk += 32){
        if (kk < 256){
            for (int i = t; i < 2048; i += 256){
                int k = i >> 6, b = i & 63;
                As[k][b] = g_H[((size_t)s*256 + kk + k)*BB + b0 + b];
            }
        } else {
            for (int i = t; i < 512; i += 256){
                int b = i >> 3, kq = i & 7;
                int kg = kk - 256 + kq*4;
                float4 v = *(const float4*)&enc[(((size_t)(b0+b))*SS + s)*CC + kg];
                int k = kq*4;
                As[k][b] = v.x; As[k+1][b] = v.y; As[k+2][b] = v.z; As[k+3][b] = v.w;
            }
        }
        for (int i = t; i < 768; i += 256){
            int c = i >> 3, kq = i & 7;
            int kg = kk + kq*4;
            float4 v = make_float4(0.f,0.f,0.f,0.f);
            if      (c < 10) v = *(const float4*)&Wpi[(size_t)c*512 + kg];
            else if (c < 50) v = *(const float4*)&Wsg[(size_t)(c-10)*512 + kg];
            else if (c < 90) v = *(const float4*)&Wmu[(size_t)(c-50)*512 + kg];
            int k = kq*4;
            Wd[k][2*c] = v.x;   Wd[k][2*c+1] = v.x;
            Wd[k+1][2*c] = v.y; Wd[k+1][2*c+1] = v.y;
            Wd[k+2][2*c] = v.z; Wd[k+2][2*c+1] = v.z;
            Wd[k+3][2*c] = v.w; Wd[k+3][2*c+1] = v.w;
        }
        __syncthreads();
        #pragma unroll 4
        for (int k = 0; k < 32; k++){
            ulonglong2 a   = *(const ulonglong2*)&As[k][bg*4];
            ulonglong2 w01 = *(const ulonglong2*)&Wd[k][cg*12];
            ulonglong2 w23 = *(const ulonglong2*)&Wd[k][cg*12+4];
            ulonglong2 w45 = *(const ulonglong2*)&Wd[k][cg*12+8];
            ffma2(acc[0][0], a.x, w01.x); ffma2(acc[0][1], a.y, w01.x);
            ffma2(acc[1][0], a.x, w01.y); ffma2(acc[1][1], a.y, w01.y);
            ffma2(acc[2][0], a.x, w23.x); ffma2(acc[2][1], a.y, w23.x);
            ffma2(acc[3][0], a.x, w23.y); ffma2(acc[3][1], a.y, w23.y);
            ffma2(acc[4][0], a.x, w45.x); ffma2(acc[4][1], a.y, w45.x);
            ffma2(acc[5][0], a.x, w45.y); ffma2(acc[5][1], a.y, w45.y);
        }
        __syncthreads();
    }
    #pragma unroll
    for (int ci = 0; ci < 6; ci++){
        int c = cg*6 + ci;
        float bias = (c < 10) ? bpi[c] : (c < 50) ? bsg[c-10] : (c < 90) ? bmu[c-50] : 0.f;
        float2 p0 = u2f2(acc[ci][0]);
        float2 p1 = u2f2(acc[ci][1]);
        Rs[bg*4+0][c] = p0.x + bias;
        Rs[bg*4+1][c] = p0.y + bias;
        Rs[bg*4+2][c] = p1.x + bias;
        Rs[bg*4+3][c] = p1.y + bias;
    }
    __syncthreads();

    if (t < 64){
        int b = b0 + t;
        float lv[10]; float m = -1e30f;
        #pragma unroll
        for (int g = 0; g < 10; g++){ lv[g] = Rs[t][g]; m = fmaxf(m, lv[g]); }
        float sum = 0.f;
        #pragma unroll
        for (int g = 0; g < 10; g++){ lv[g] = expf(lv[g]-m); sum += lv[g]; }
        float inv = 1.f/sum;
        size_t base = (size_t)OUT_PI + ((size_t)b*SS + s)*10;
        #pragma unroll
        for (int g = 0; g < 10; g++) out[base + g] = lv[g]*inv;
    }
    for (int i = t; i < 64*40; i += 256){
        int row = i/40, j = i - row*40;
        int b = b0 + row;
        float x  = Rs[row][10+j];
        float xm = Rs[row][50+j];
        size_t base = ((size_t)b*SS + s)*40 + j;
        out[(size_t)OUT_SG + base] = (x > 0.f) ? (x + 1.f) : expf(x);
        out[(size_t)OUT_MU + base] = xm;
    }
}

// ---------------- kernel 5: tgt copy + duration mask ------------------------
__global__ void tail_kernel(const float* __restrict__ tgt,
                            const int* __restrict__ dur,
                            float* __restrict__ out){
    if (blockIdx.x < 1024){
        int idx = blockIdx.x*256 + threadIdx.x;
        out[idx] = tgt[idx];
    } else {
        int b = blockIdx.x - 1024;
        __shared__ int cnt;
        if (threadIdx.x == 0) cnt = 0;
        __syncthreads();
        int local = 0;
        for (int s = threadIdx.x; s < SS; s += 256) local += (dur[b*SS + s] > 0) ? 1 : 0;
        #pragma unroll
        for (int o = 16; o; o >>= 1) local += __shfl_down_sync(0xffffffffu, local, o);
        if ((threadIdx.x & 31) == 0) atomicAdd(&cnt, local);
        __syncthreads();
        int c = cnt;
        for (int s = threadIdx.x; s < SS; s += 256)
            out[OUT_MASK + b*SS + s] = (s >= c) ? 1.f : 0.f;
    }
}

// ---------------- launch -----------------------------------------------------
#define REC_SMEM ((12288 + 6144 + 16384 + 16384 + 6144 + 768) * (int)sizeof(float))

extern "C" void kernel_launch(void* const* d_in, const int* in_sizes, int n_in,
                              void* d_out, int out_size)
{
    const float* enc   = (const float*)d_in[0];
    const float* tgt   = (const float*)d_in[1];
    const int*   dur   = (const int*)  d_in[2];
    const float* W_pre = (const float*)d_in[3];
    const float* b_pre = (const float*)d_in[4];
    const float* Wih0  = (const float*)d_in[5];
    const float* Whh0  = (const float*)d_in[6];
    const float* bih0  = (const float*)d_in[7];
    const float* bhh0  = (const float*)d_in[8];
    const float* Wih1  = (const float*)d_in[9];
    const float* Whh1  = (const float*)d_in[10];
    const float* bih1  = (const float*)d_in[11];
    const float* bhh1  = (const float*)d_in[12];
    const float* Wpi   = (const float*)d_in[13];
    const float* bpi   = (const float*)d_in[14];
    const float* Wsg   = (const float*)d_in[15];
    const float* bsg   = (const float*)d_in[16];
    const float* Wmu   = (const float*)d_in[17];
    const float* bmu   = (const float*)d_in[18];
    float* out = (float*)d_out;

    init_kernel<<<128, 256>>>();

    prenet_kernel<<<(BB*SS*DOO + 255)/256, 256>>>(tgt, W_pre, b_pre);

    dim3 g2(2, 12, SS);
    gi0_gemm<<<g2, 256>>>(enc, Wih0, bih0);

    cudaFuncSetAttribute(rec_kernel, cudaFuncAttributeMaxDynamicSharedMemorySize, REC_SMEM);
    rec_kernel<<<NCTA, TPB, REC_SMEM>>>(Whh0, bhh0, Wih1, bih1, Whh1, bhh1);

    dim3 g4(2, SS);
    out_gemm<<<g4, 256>>>(enc, Wpi, bpi, Wsg, bsg, Wmu, bmu, out);

    tail_kernel<<<1024 + BB, 256>>>(tgt, dur, out);
}